// round 1
// baseline (speedup 1.0000x reference)
#include <cuda_runtime.h>
#include <cstdint>

#define BATCH 4096
#define T 64
#define D 128
#define TD 8192

// Scratch (allocation-free rule: __device__ globals)
__device__ float g_h0[BATCH * D];                 // split-K partial 0
__device__ float g_h1[BATCH * D];                 // split-K partial 1
__device__ float g_ypart[(size_t)BATCH * TD];     // X + X_dot (attention out + residual)

// ---------------- tf32 mma helpers ----------------
__device__ __forceinline__ uint32_t f2tf32(float f) {
    uint32_t r;
    asm("cvt.rna.tf32.f32 %0, %1;" : "=r"(r) : "f"(f));
    return r;
}

__device__ __forceinline__ void mma_tf32(float* c,
    uint32_t a0, uint32_t a1, uint32_t a2, uint32_t a3,
    uint32_t b0, uint32_t b1)
{
    asm volatile(
        "mma.sync.aligned.m16n8k8.row.col.f32.tf32.tf32.f32 "
        "{%0,%1,%2,%3}, {%4,%5,%6,%7}, {%8,%9}, {%0,%1,%2,%3};\n"
        : "+f"(c[0]), "+f"(c[1]), "+f"(c[2]), "+f"(c[3])
        : "r"(a0), "r"(a1), "r"(a2), "r"(a3), "r"(b0), "r"(b1));
}

// ============================================================
// Kernel 1: h_part[split] = Xf(4096x8192) @ W1^T(8192x128), split-K=2
// grid (64, 2), 256 threads. M_TILE=64, K_TILE=32.
// ============================================================
__global__ void __launch_bounds__(256) gemm1_kernel(
    const float* __restrict__ X, const float* __restrict__ W1)
{
    __shared__ float As[64][40];    // [m][k], stride 40 (8 mod 32)
    __shared__ float Bs[32][136];   // [k][n], stride 136 (8 mod 32)

    const int m0     = blockIdx.x * 64;
    const int k_base = blockIdx.y * 4096;
    const int tid  = threadIdx.x;
    const int wid  = tid >> 5, lane = tid & 31;
    const int g    = lane >> 2, tg = lane & 3;
    const int wm   = wid & 3,  wn  = wid >> 2;   // 4x2 warp grid, warp tile 16x64

    float acc[8][4];
#pragma unroll
    for (int i = 0; i < 8; i++)
#pragma unroll
        for (int j = 0; j < 4; j++) acc[i][j] = 0.f;

    for (int kt = 0; kt < 128; kt++) {
        const int kk = k_base + kt * 32;
        // A: 64x32 tile of X, float4 coalesced
#pragma unroll
        for (int i = 0; i < 2; i++) {
            int q = tid + i * 256;             // 512 float4
            int r = q >> 3, c4 = q & 7;
            float4 v = *reinterpret_cast<const float4*>(
                X + (size_t)(m0 + r) * TD + kk + c4 * 4);
            *reinterpret_cast<float4*>(&As[r][c4 * 4]) = v;
        }
        // B: Bs[k][n] = W1[n][kk+k]  (transpose via smem)
#pragma unroll
        for (int i = 0; i < 4; i++) {
            int q = tid + i * 256;             // 1024 float4
            int n = q >> 3, c4 = q & 7;
            float4 v = *reinterpret_cast<const float4*>(
                W1 + (size_t)n * TD + kk + c4 * 4);
            Bs[c4 * 4 + 0][n] = v.x; Bs[c4 * 4 + 1][n] = v.y;
            Bs[c4 * 4 + 2][n] = v.z; Bs[c4 * 4 + 3][n] = v.w;
        }
        __syncthreads();
#pragma unroll
        for (int ks = 0; ks < 4; ks++) {
            uint32_t a0 = f2tf32(As[wm * 16 + g    ][ks * 8 + tg    ]);
            uint32_t a1 = f2tf32(As[wm * 16 + g + 8][ks * 8 + tg    ]);
            uint32_t a2 = f2tf32(As[wm * 16 + g    ][ks * 8 + tg + 4]);
            uint32_t a3 = f2tf32(As[wm * 16 + g + 8][ks * 8 + tg + 4]);
#pragma unroll
            for (int nt = 0; nt < 8; nt++) {
                uint32_t b0 = f2tf32(Bs[ks * 8 + tg    ][wn * 64 + nt * 8 + g]);
                uint32_t b1 = f2tf32(Bs[ks * 8 + tg + 4][wn * 64 + nt * 8 + g]);
                mma_tf32(acc[nt], a0, a1, a2, a3, b0, b1);
            }
        }
        __syncthreads();
    }

    float* outp = blockIdx.y ? g_h1 : g_h0;
#pragma unroll
    for (int nt = 0; nt < 8; nt++) {
        int col = wn * 64 + nt * 8 + tg * 2;
        int row = m0 + wm * 16 + g;
        outp[(size_t)row * D + col]           = acc[nt][0];
        outp[(size_t)row * D + col + 1]       = acc[nt][1];
        outp[(size_t)(row + 8) * D + col]     = acc[nt][2];
        outp[(size_t)(row + 8) * D + col + 1] = acc[nt][3];
    }
}

// ============================================================
// Kernel 2: per-batch attention, fused: scores -> softmax -> attn@X -> +X
// grid 4096, 256 threads, dynamic smem: Xs[64][136] + Ss[64][72]
// ============================================================
__global__ void __launch_bounds__(256) attn_kernel(const float* __restrict__ X)
{
    extern __shared__ float sm[];
    float (*Xs)[136] = reinterpret_cast<float(*)[136]>(sm);
    float (*Ss)[72]  = reinterpret_cast<float(*)[72]>(sm + 64 * 136);

    const int b = blockIdx.x;
    const float* Xb = X + (size_t)b * TD;
    const int tid = threadIdx.x, wid = tid >> 5, lane = tid & 31;
    const int g = lane >> 2, tg = lane & 3;

    // Load X_b (64x128)
#pragma unroll
    for (int i = 0; i < 8; i++) {
        int q = tid + i * 256;                 // 2048 float4
        int r = q >> 5, c4 = q & 31;
        float4 v = *reinterpret_cast<const float4*>(Xb + r * D + c4 * 4);
        *reinterpret_cast<float4*>(&Xs[r][c4 * 4]) = v;
    }
    __syncthreads();

    // scores = X_b @ X_b^T * scale, warp grid 4(m) x 2(n), warp tile 16x32
    {
        const int wm = wid & 3, wn = wid >> 2;
        float acc[4][4];
#pragma unroll
        for (int i = 0; i < 4; i++)
#pragma unroll
            for (int j = 0; j < 4; j++) acc[i][j] = 0.f;
#pragma unroll
        for (int ks = 0; ks < 16; ks++) {
            uint32_t a0 = f2tf32(Xs[wm * 16 + g    ][ks * 8 + tg    ]);
            uint32_t a1 = f2tf32(Xs[wm * 16 + g + 8][ks * 8 + tg    ]);
            uint32_t a2 = f2tf32(Xs[wm * 16 + g    ][ks * 8 + tg + 4]);
            uint32_t a3 = f2tf32(Xs[wm * 16 + g + 8][ks * 8 + tg + 4]);
#pragma unroll
            for (int nt = 0; nt < 4; nt++) {
                uint32_t b0 = f2tf32(Xs[wn * 32 + nt * 8 + g][ks * 8 + tg    ]);
                uint32_t b1 = f2tf32(Xs[wn * 32 + nt * 8 + g][ks * 8 + tg + 4]);
                mma_tf32(acc[nt], a0, a1, a2, a3, b0, b1);
            }
        }
        const float scale = 0.0883883476483184f;  // 128^-0.5
#pragma unroll
        for (int nt = 0; nt < 4; nt++) {
            int col = wn * 32 + nt * 8 + tg * 2, row = wm * 16 + g;
            Ss[row][col]         = acc[nt][0] * scale;
            Ss[row][col + 1]     = acc[nt][1] * scale;
            Ss[row + 8][col]     = acc[nt][2] * scale;
            Ss[row + 8][col + 1] = acc[nt][3] * scale;
        }
    }
    __syncthreads();

    // softmax: warp wid owns rows [wid*8, wid*8+8), in-place in Ss
    for (int rr = 0; rr < 8; rr++) {
        int r = wid * 8 + rr;
        float v0 = Ss[r][lane * 2], v1 = Ss[r][lane * 2 + 1];
        float m = fmaxf(v0, v1);
#pragma unroll
        for (int o = 16; o > 0; o >>= 1) m = fmaxf(m, __shfl_xor_sync(~0u, m, o));
        float e0 = __expf(v0 - m), e1 = __expf(v1 - m);
        float s = e0 + e1;
#pragma unroll
        for (int o = 16; o > 0; o >>= 1) s += __shfl_xor_sync(~0u, s, o);
        float inv = 1.f / s;
        Ss[r][lane * 2] = e0 * inv; Ss[r][lane * 2 + 1] = e1 * inv;
    }
    __syncthreads();

    // X_dot = attn @ X_b (64x128, K=64), warp grid 4x2, warp tile 16x64
    const int wm = wid & 3, wn = wid >> 2;
    float acc[8][4];
#pragma unroll
    for (int i = 0; i < 8; i++)
#pragma unroll
        for (int j = 0; j < 4; j++) acc[i][j] = 0.f;
#pragma unroll
    for (int ks = 0; ks < 8; ks++) {
        uint32_t a0 = f2tf32(Ss[wm * 16 + g    ][ks * 8 + tg    ]);
        uint32_t a1 = f2tf32(Ss[wm * 16 + g + 8][ks * 8 + tg    ]);
        uint32_t a2 = f2tf32(Ss[wm * 16 + g    ][ks * 8 + tg + 4]);
        uint32_t a3 = f2tf32(Ss[wm * 16 + g + 8][ks * 8 + tg + 4]);
#pragma unroll
        for (int nt = 0; nt < 8; nt++) {
            uint32_t b0 = f2tf32(Xs[ks * 8 + tg    ][wn * 64 + nt * 8 + g]);
            uint32_t b1 = f2tf32(Xs[ks * 8 + tg + 4][wn * 64 + nt * 8 + g]);
            mma_tf32(acc[nt], a0, a1, a2, a3, b0, b1);
        }
    }
    float* yp = g_ypart + (size_t)b * TD;
#pragma unroll
    for (int nt = 0; nt < 8; nt++) {
        int col = wn * 64 + nt * 8 + tg * 2, row = wm * 16 + g;
        yp[row * D + col]           = acc[nt][0] + Xs[row][col];
        yp[row * D + col + 1]       = acc[nt][1] + Xs[row][col + 1];
        yp[(row + 8) * D + col]     = acc[nt][2] + Xs[row + 8][col];
        yp[(row + 8) * D + col + 1] = acc[nt][3] + Xs[row + 8][col + 1];
    }
}

// ============================================================
// Kernel 3: out = LN( ypart + b2 + relu(h0+h1+b1) @ W2^T ) * gamma + beta
// grid (32 m-tiles, 64 tokens), 256 threads.
// M_TILE=128 batches, N=128 (one token's d), K=128.
// dynamic smem: As[128][136] (aliased to ys in epilogue) + Bs[128][136]
// ============================================================
__global__ void __launch_bounds__(256) gemm2_ln_kernel(
    const float* __restrict__ W2, const float* __restrict__ b1,
    const float* __restrict__ b2, const float* __restrict__ gamma,
    const float* __restrict__ beta, float* __restrict__ out)
{
    extern __shared__ float sm[];
    float (*As)[136] = reinterpret_cast<float(*)[136]>(sm);
    float (*Bs)[136] = reinterpret_cast<float(*)[136]>(sm + 128 * 136);

    const int m0 = blockIdx.x * 128;
    const int t  = blockIdx.y;
    const int tid = threadIdx.x, wid = tid >> 5, lane = tid & 31;
    const int g = lane >> 2, tg = lane & 3;

    // A tile = relu(h0 + h1 + b1), fused here (no separate relu pass)
#pragma unroll
    for (int i = 0; i < 16; i++) {
        int q = tid + i * 256;                 // 4096 float4
        int r = q >> 5, c4 = q & 31;
        size_t off = (size_t)(m0 + r) * D + c4 * 4;
        float4 u  = *reinterpret_cast<const float4*>(g_h0 + off);
        float4 v  = *reinterpret_cast<const float4*>(g_h1 + off);
        float4 bb = *reinterpret_cast<const float4*>(b1 + c4 * 4);
        float4 w;
        w.x = fmaxf(u.x + v.x + bb.x, 0.f);
        w.y = fmaxf(u.y + v.y + bb.y, 0.f);
        w.z = fmaxf(u.z + v.z + bb.z, 0.f);
        w.w = fmaxf(u.w + v.w + bb.w, 0.f);
        *reinterpret_cast<float4*>(&As[r][c4 * 4]) = w;
    }
    // B tile: Bs[k][n] = W2[(t*128+n)*128 + k]  (rows of W2 are contiguous in k)
#pragma unroll
    for (int i = 0; i < 16; i++) {
        int q = tid + i * 256;
        int n = q >> 5, c4 = q & 31;
        float4 v = *reinterpret_cast<const float4*>(
            W2 + (size_t)(t * D + n) * D + c4 * 4);
        Bs[c4 * 4 + 0][n] = v.x; Bs[c4 * 4 + 1][n] = v.y;
        Bs[c4 * 4 + 2][n] = v.z; Bs[c4 * 4 + 3][n] = v.w;
    }
    __syncthreads();

    // warp wid owns rows [wid*16, +16), all 128 cols (16 n-tiles)
    float acc[16][4];
#pragma unroll
    for (int i = 0; i < 16; i++)
#pragma unroll
        for (int j = 0; j < 4; j++) acc[i][j] = 0.f;
#pragma unroll
    for (int ks = 0; ks < 16; ks++) {
        uint32_t a0 = f2tf32(As[wid * 16 + g    ][ks * 8 + tg    ]);
        uint32_t a1 = f2tf32(As[wid * 16 + g + 8][ks * 8 + tg    ]);
        uint32_t a2 = f2tf32(As[wid * 16 + g    ][ks * 8 + tg + 4]);
        uint32_t a3 = f2tf32(As[wid * 16 + g + 8][ks * 8 + tg + 4]);
#pragma unroll
        for (int nt = 0; nt < 16; nt++) {
            uint32_t b0 = f2tf32(Bs[ks * 8 + tg    ][nt * 8 + g]);
            uint32_t b1r = f2tf32(Bs[ks * 8 + tg + 4][nt * 8 + g]);
            mma_tf32(acc[nt], a0, a1, a2, a3, b0, b1r);
        }
    }
    __syncthreads();   // all mma reads of As done; now alias As as ys

    float (*ys)[136] = As;
    // ys = ypart + b2 (coalesced)
#pragma unroll
    for (int i = 0; i < 16; i++) {
        int q = tid + i * 256;
        int r = q >> 5, c4 = q & 31;
        float4 v  = *reinterpret_cast<const float4*>(
            g_ypart + (size_t)(m0 + r) * TD + t * D + c4 * 4);
        float4 bb = *reinterpret_cast<const float4*>(b2 + t * D + c4 * 4);
        v.x += bb.x; v.y += bb.y; v.z += bb.z; v.w += bb.w;
        *reinterpret_cast<float4*>(&ys[r][c4 * 4]) = v;
    }
    __syncthreads();
    // accumulate GEMM result into ys (each element owned by exactly one thread)
#pragma unroll
    for (int nt = 0; nt < 16; nt++) {
        int col = nt * 8 + tg * 2, row = wid * 16 + g;
        ys[row][col]         += acc[nt][0];
        ys[row][col + 1]     += acc[nt][1];
        ys[row + 8][col]     += acc[nt][2];
        ys[row + 8][col + 1] += acc[nt][3];
    }
    __syncthreads();

    // LayerNorm over 128 d per row; warp wid owns rows [wid*16, +16)
    float4 gm = *reinterpret_cast<const float4*>(gamma + lane * 4);
    float4 bt = *reinterpret_cast<const float4*>(beta + lane * 4);
    for (int rr = 0; rr < 16; rr++) {
        int r = wid * 16 + rr;
        float4 v = *reinterpret_cast<float4*>(&ys[r][lane * 4]);
        float s = v.x + v.y + v.z + v.w;
#pragma unroll
        for (int o = 16; o > 0; o >>= 1) s += __shfl_xor_sync(~0u, s, o);
        float mu = s * (1.f / 128.f);
        float dx = v.x - mu, dy = v.y - mu, dz = v.z - mu, dw = v.w - mu;
        float q2 = dx * dx + dy * dy + dz * dz + dw * dw;
#pragma unroll
        for (int o = 16; o > 0; o >>= 1) q2 += __shfl_xor_sync(~0u, q2, o);
        float rs = rsqrtf(q2 * (1.f / 128.f) + 1e-5f);
        float4 o4;
        o4.x = dx * rs * gm.x + bt.x;
        o4.y = dy * rs * gm.y + bt.y;
        o4.z = dz * rs * gm.z + bt.z;
        o4.w = dw * rs * gm.w + bt.w;
        *reinterpret_cast<float4*>(
            out + (size_t)(m0 + r) * TD + t * D + lane * 4) = o4;
    }
}

// ============================================================
extern "C" void kernel_launch(void* const* d_in, const int* in_sizes, int n_in,
                              void* d_out, int out_size)
{
    const float* X     = (const float*)d_in[0];
    const float* W1    = (const float*)d_in[1];
    const float* b1    = (const float*)d_in[2];
    const float* W2    = (const float*)d_in[3];
    const float* b2    = (const float*)d_in[4];
    const float* gamma = (const float*)d_in[5];
    const float* beta  = (const float*)d_in[6];
    float* out = (float*)d_out;

    const int smem_attn  = (64 * 136 + 64 * 72) * 4;     // 53,248 B
    const int smem_gemm2 = (2 * 128 * 136) * 4;          // 139,264 B
    cudaFuncSetAttribute(attn_kernel,
        cudaFuncAttributeMaxDynamicSharedMemorySize, smem_attn);
    cudaFuncSetAttribute(gemm2_ln_kernel,
        cudaFuncAttributeMaxDynamicSharedMemorySize, smem_gemm2);

    gemm1_kernel<<<dim3(64, 2), 256>>>(X, W1);
    attn_kernel<<<4096, 256, smem_attn>>>(X);
    gemm2_ln_kernel<<<dim3(32, 64), 256, smem_gemm2>>>(W2, b1, b2, gamma, beta, out);
}

// round 2
// speedup vs baseline: 2.0574x; 2.0574x over previous
#include <cuda_runtime.h>
#include <cstdint>

#define BATCH 4096
#define T 64
#define D 128
#define TD 8192
#define SPLITK 8

// Scratch (__device__ globals per allocation-free rule)
__device__ float g_hp[(size_t)SPLITK * BATCH * D];      // gemm1 split-K partials (16MB)
__device__ unsigned g_ht[BATCH * D];                    // relu(h)+b1, tf32 bits (2MB)
__device__ float g_ypart[(size_t)BATCH * TD];           // X + X_dot (128MB)

// ---------------- tf32 helpers ----------------
__device__ __forceinline__ unsigned f2tf32(float f) {
    unsigned r;
    asm("cvt.rna.tf32.f32 %0, %1;" : "=r"(r) : "f"(f));
    return r;
}
__device__ __forceinline__ uint4 cvt4(float4 v) {
    uint4 u;
    u.x = f2tf32(v.x); u.y = f2tf32(v.y); u.z = f2tf32(v.z); u.w = f2tf32(v.w);
    return u;
}
__device__ __forceinline__ void mma_tf32(float* c,
    unsigned a0, unsigned a1, unsigned a2, unsigned a3, unsigned b0, unsigned b1)
{
    asm volatile(
        "mma.sync.aligned.m16n8k8.row.col.f32.tf32.tf32.f32 "
        "{%0,%1,%2,%3}, {%4,%5,%6,%7}, {%8,%9}, {%0,%1,%2,%3};\n"
        : "+f"(c[0]), "+f"(c[1]), "+f"(c[2]), "+f"(c[3])
        : "r"(a0), "r"(a1), "r"(a2), "r"(a3), "r"(b0), "r"(b1));
}

// ============================================================
// Kernel 1: split-K GEMM  h_part = Xf(4096x8192) @ W1^T(8192x128)
// grid (64, 8), 256 thr. M_TILE=64, K chunk=1024, K_TILE=32.
// As stride 36 (=4 mod 32, conflict-free A frags); Bs stride 136 + XOR swizzle.
// Register-staged double buffering.
// ============================================================
__global__ void __launch_bounds__(256) gemm1_kernel(
    const float* __restrict__ X, const float* __restrict__ W1)
{
    __shared__ unsigned As[64][36];
    __shared__ unsigned Bs[32][136];

    const int m0 = blockIdx.x * 64;
    const int k0 = blockIdx.y * 1024;
    const int tid = threadIdx.x;
    const int wid = tid >> 5, lane = tid & 31;
    const int g = lane >> 2, tg = lane & 3;
    const int wm = wid & 3, wn = wid >> 2;     // 4x2 warps, warp tile 16x64

    float acc[8][4];
#pragma unroll
    for (int i = 0; i < 8; i++)
#pragma unroll
        for (int j = 0; j < 4; j++) acc[i][j] = 0.f;

    // fill mappings
    const int ar = tid >> 3, ac4 = tid & 7;            // A: +i*32 rows
    const int bn = tid >> 3, bc4 = tid & 7;            // B: +i*32 n's
    float4 a_st[2], b_st[4];

#define G1_LOAD(KK)                                                          \
    {                                                                        \
        _Pragma("unroll")                                                    \
        for (int i = 0; i < 2; i++)                                          \
            a_st[i] = *reinterpret_cast<const float4*>(                      \
                X + (size_t)(m0 + ar + i * 32) * TD + (KK) + ac4 * 4);       \
        _Pragma("unroll")                                                    \
        for (int i = 0; i < 4; i++)                                          \
            b_st[i] = *reinterpret_cast<const float4*>(                      \
                W1 + (size_t)(bn + i * 32) * TD + (KK) + bc4 * 4);           \
    }
#define G1_STORE()                                                           \
    {                                                                        \
        _Pragma("unroll")                                                    \
        for (int i = 0; i < 2; i++)                                          \
            *reinterpret_cast<uint4*>(&As[ar + i * 32][ac4 * 4]) = cvt4(a_st[i]); \
        _Pragma("unroll")                                                    \
        for (int i = 0; i < 4; i++) {                                        \
            uint4 u = cvt4(b_st[i]);                                         \
            int pc = (bn + i * 32) ^ (bc4 * 4);                              \
            Bs[bc4 * 4 + 0][pc] = u.x; Bs[bc4 * 4 + 1][pc] = u.y;            \
            Bs[bc4 * 4 + 2][pc] = u.z; Bs[bc4 * 4 + 3][pc] = u.w;            \
        }                                                                    \
    }

    G1_LOAD(k0);
    G1_STORE();
    __syncthreads();

    for (int kt = 0; kt < 32; kt++) {
        if (kt < 31) G1_LOAD(k0 + (kt + 1) * 32);
#pragma unroll
        for (int ks = 0; ks < 4; ks++) {
            unsigned a0 = As[wm * 16 + g    ][ks * 8 + tg    ];
            unsigned a1 = As[wm * 16 + g + 8][ks * 8 + tg    ];
            unsigned a2 = As[wm * 16 + g    ][ks * 8 + tg + 4];
            unsigned a3 = As[wm * 16 + g + 8][ks * 8 + tg + 4];
            const int c0 = 4 * ((2 * ks) & 7), c1 = 4 * ((2 * ks + 1) & 7);
#pragma unroll
            for (int nt = 0; nt < 8; nt++) {
                int col = wn * 64 + nt * 8 + g;
                unsigned b0 = Bs[ks * 8 + tg    ][col ^ c0];
                unsigned b1 = Bs[ks * 8 + tg + 4][col ^ c1];
                mma_tf32(acc[nt], a0, a1, a2, a3, b0, b1);
            }
        }
        __syncthreads();
        if (kt < 31) { G1_STORE(); __syncthreads(); }
    }

    float* outp = g_hp + (size_t)blockIdx.y * BATCH * D;
#pragma unroll
    for (int nt = 0; nt < 8; nt++) {
        int col = wn * 64 + nt * 8 + tg * 2;
        int row = m0 + wm * 16 + g;
        *reinterpret_cast<float2*>(outp + (size_t)row * D + col) =
            make_float2(acc[nt][0], acc[nt][1]);
        *reinterpret_cast<float2*>(outp + (size_t)(row + 8) * D + col) =
            make_float2(acc[nt][2], acc[nt][3]);
    }
}

// ============================================================
// Kernel 1b: g_ht = tf32( relu( sum_p g_hp[p] + b1 ) )
// ============================================================
__global__ void __launch_bounds__(256) reduce_relu_kernel(const float* __restrict__ b1)
{
    const int idx = blockIdx.x * 256 + threadIdx.x;       // float4 index
    const size_t off = (size_t)idx * 4;
    float4 s = *reinterpret_cast<const float4*>(b1 + (off & 127));
#pragma unroll
    for (int p = 0; p < SPLITK; p++) {
        float4 v = *reinterpret_cast<const float4*>(g_hp + (size_t)p * BATCH * D + off);
        s.x += v.x; s.y += v.y; s.z += v.z; s.w += v.w;
    }
    s.x = fmaxf(s.x, 0.f); s.y = fmaxf(s.y, 0.f);
    s.z = fmaxf(s.z, 0.f); s.w = fmaxf(s.w, 0.f);
    *reinterpret_cast<uint4*>(g_ht + off) = cvt4(s);
}

// ============================================================
// Kernel 2: per-batch attention: scores -> softmax -> attn@X -> +X
// grid 4096, 256 thr. Xt: tf32 bits, stride 132 (=4 mod 32).
// Ss: fp32 scores then tf32 probs, stride 68 (=4 mod 32).
// ============================================================
__global__ void __launch_bounds__(256) attn_kernel(const float* __restrict__ X)
{
    extern __shared__ unsigned sm_u[];
    unsigned (*Xt)[132] = reinterpret_cast<unsigned(*)[132]>(sm_u);
    float    (*Ss)[68]  = reinterpret_cast<float(*)[68]>(sm_u + 64 * 132);
    unsigned (*Ssu)[68] = reinterpret_cast<unsigned(*)[68]>(sm_u + 64 * 132);

    const int b = blockIdx.x;
    const float* Xb = X + (size_t)b * TD;
    const int tid = threadIdx.x, wid = tid >> 5, lane = tid & 31;
    const int g = lane >> 2, tg = lane & 3;

    // Load + convert X_b (64x128) to tf32 bits
#pragma unroll
    for (int i = 0; i < 8; i++) {
        int q = tid + i * 256;
        int r = q >> 5, c4 = q & 31;
        float4 v = *reinterpret_cast<const float4*>(Xb + r * D + c4 * 4);
        *reinterpret_cast<uint4*>(&Xt[r][c4 * 4]) = cvt4(v);
    }
    __syncthreads();

    // scores = X X^T * scale; warp grid 4(m) x 2(n), warp tile 16x32
    {
        const int wm = wid & 3, wn = wid >> 2;
        float acc[4][4];
#pragma unroll
        for (int i = 0; i < 4; i++)
#pragma unroll
            for (int j = 0; j < 4; j++) acc[i][j] = 0.f;
#pragma unroll
        for (int ks = 0; ks < 16; ks++) {
            unsigned a0 = Xt[wm * 16 + g    ][ks * 8 + tg    ];
            unsigned a1 = Xt[wm * 16 + g + 8][ks * 8 + tg    ];
            unsigned a2 = Xt[wm * 16 + g    ][ks * 8 + tg + 4];
            unsigned a3 = Xt[wm * 16 + g + 8][ks * 8 + tg + 4];
#pragma unroll
            for (int nt = 0; nt < 4; nt++) {
                unsigned b0 = Xt[wn * 32 + nt * 8 + g][ks * 8 + tg    ];
                unsigned b1 = Xt[wn * 32 + nt * 8 + g][ks * 8 + tg + 4];
                mma_tf32(acc[nt], a0, a1, a2, a3, b0, b1);
            }
        }
        const float scale = 0.0883883476483184f;   // 128^-0.5
#pragma unroll
        for (int nt = 0; nt < 4; nt++) {
            int col = wn * 32 + nt * 8 + tg * 2, row = wm * 16 + g;
            Ss[row][col]         = acc[nt][0] * scale;
            Ss[row][col + 1]     = acc[nt][1] * scale;
            Ss[row + 8][col]     = acc[nt][2] * scale;
            Ss[row + 8][col + 1] = acc[nt][3] * scale;
        }
    }
    __syncthreads();

    // softmax rows -> write tf32 prob bits in place
    for (int rr = 0; rr < 8; rr++) {
        int r = wid * 8 + rr;
        float v0 = Ss[r][lane * 2], v1 = Ss[r][lane * 2 + 1];
        float m = fmaxf(v0, v1);
#pragma unroll
        for (int o = 16; o > 0; o >>= 1) m = fmaxf(m, __shfl_xor_sync(~0u, m, o));
        float e0 = __expf(v0 - m), e1 = __expf(v1 - m);
        float s = e0 + e1;
#pragma unroll
        for (int o = 16; o > 0; o >>= 1) s += __shfl_xor_sync(~0u, s, o);
        float inv = 1.f / s;
        Ssu[r][lane * 2]     = f2tf32(e0 * inv);
        Ssu[r][lane * 2 + 1] = f2tf32(e1 * inv);
    }
    __syncthreads();

    // X_dot = attn @ X (64x128, K=64); warp grid 4x2, warp tile 16x64
    const int wm = wid & 3, wn = wid >> 2;
    float acc[8][4];
#pragma unroll
    for (int i = 0; i < 8; i++)
#pragma unroll
        for (int j = 0; j < 4; j++) acc[i][j] = 0.f;
#pragma unroll
    for (int ks = 0; ks < 8; ks++) {
        unsigned a0 = Ssu[wm * 16 + g    ][ks * 8 + tg    ];
        unsigned a1 = Ssu[wm * 16 + g + 8][ks * 8 + tg    ];
        unsigned a2 = Ssu[wm * 16 + g    ][ks * 8 + tg + 4];
        unsigned a3 = Ssu[wm * 16 + g + 8][ks * 8 + tg + 4];
#pragma unroll
        for (int nt = 0; nt < 8; nt++) {
            unsigned b0 = Xt[ks * 8 + tg    ][wn * 64 + nt * 8 + g];
            unsigned b1 = Xt[ks * 8 + tg + 4][wn * 64 + nt * 8 + g];
            mma_tf32(acc[nt], a0, a1, a2, a3, b0, b1);
        }
    }
    // epilogue: + X (global re-read, L2-hot), write ypart
    float* yp = g_ypart + (size_t)b * TD;
#pragma unroll
    for (int nt = 0; nt < 8; nt++) {
        int col = wn * 64 + nt * 8 + tg * 2, row = wm * 16 + g;
        float2 x0 = *reinterpret_cast<const float2*>(Xb + row * D + col);
        float2 x1 = *reinterpret_cast<const float2*>(Xb + (row + 8) * D + col);
        *reinterpret_cast<float2*>(yp + row * D + col) =
            make_float2(acc[nt][0] + x0.x, acc[nt][1] + x0.y);
        *reinterpret_cast<float2*>(yp + (row + 8) * D + col) =
            make_float2(acc[nt][2] + x1.x, acc[nt][3] + x1.y);
    }
}

// ============================================================
// Kernel 3: out = LN( ypart + b2 + g_ht @ W2^T ) * gamma + beta
// grid (64 m-tiles, 64 tokens), 256 thr. M_TILE=64, N=128, K=128.
// As: tf32 bits from g_ht, stride 132; Bs: stride 136 + XOR swizzle.
// ============================================================
__global__ void __launch_bounds__(256) gemm2_ln_kernel(
    const float* __restrict__ W2, const float* __restrict__ b2,
    const float* __restrict__ gamma, const float* __restrict__ beta,
    float* __restrict__ out)
{
    extern __shared__ unsigned sm_u[];
    unsigned (*As)[132] = reinterpret_cast<unsigned(*)[132]>(sm_u);
    unsigned (*Bs)[136] = reinterpret_cast<unsigned(*)[136]>(sm_u + 64 * 132);

    const int m0 = blockIdx.x * 64;
    const int t  = blockIdx.y;
    const int tid = threadIdx.x, wid = tid >> 5, lane = tid & 31;
    const int g = lane >> 2, tg = lane & 3;
    const int wm = wid & 3, wn = wid >> 2;     // warp tile 16x64

    // A fill: straight uint4 copy of pre-converted tf32 relu(h)
#pragma unroll
    for (int i = 0; i < 8; i++) {
        int q = tid + i * 256;
        int r = q >> 5, c4 = q & 31;
        *reinterpret_cast<uint4*>(&As[r][c4 * 4]) =
            *reinterpret_cast<const uint4*>(g_ht + (size_t)(m0 + r) * D + c4 * 4);
    }
    // B fill: Bs[k][n^swz] = tf32(W2[(t*128+n)*128 + k]); coalesced + conflict-free
#pragma unroll
    for (int i = 0; i < 16; i++) {
        int q  = tid + i * 256;
        int kq = (q & 7) + (q >> 10) * 8;      // float4 index along k (0..31)
        int n  = (q >> 3) & 127;
        float4 v = *reinterpret_cast<const float4*>(
            W2 + (size_t)(t * D + n) * D + kq * 4);
        uint4 u = cvt4(v);
        int pc = n ^ (4 * (kq & 7));
        Bs[kq * 4 + 0][pc] = u.x; Bs[kq * 4 + 1][pc] = u.y;
        Bs[kq * 4 + 2][pc] = u.z; Bs[kq * 4 + 3][pc] = u.w;
    }
    __syncthreads();

    float acc[8][4];
#pragma unroll
    for (int i = 0; i < 8; i++)
#pragma unroll
        for (int j = 0; j < 4; j++) acc[i][j] = 0.f;
#pragma unroll
    for (int ks = 0; ks < 16; ks++) {
        unsigned a0 = As[wm * 16 + g    ][ks * 8 + tg    ];
        unsigned a1 = As[wm * 16 + g + 8][ks * 8 + tg    ];
        unsigned a2 = As[wm * 16 + g    ][ks * 8 + tg + 4];
        unsigned a3 = As[wm * 16 + g + 8][ks * 8 + tg + 4];
        const int c0 = 4 * ((2 * ks) & 7), c1 = 4 * ((2 * ks + 1) & 7);
#pragma unroll
        for (int nt = 0; nt < 8; nt++) {
            int col = wn * 64 + nt * 8 + g;
            unsigned b0 = Bs[ks * 8 + tg    ][col ^ c0];
            unsigned b1 = Bs[ks * 8 + tg + 4][col ^ c1];
            mma_tf32(acc[nt], a0, a1, a2, a3, b0, b1);
        }
    }
    __syncthreads();     // As reads done; alias as fp32 ys

    float (*ys)[132] = reinterpret_cast<float(*)[132]>(As);
    // ys = ypart + b2
#pragma unroll
    for (int i = 0; i < 8; i++) {
        int q = tid + i * 256;
        int r = q >> 5, c4 = q & 31;
        float4 v  = *reinterpret_cast<const float4*>(
            g_ypart + (size_t)(m0 + r) * TD + t * D + c4 * 4);
        float4 bb = *reinterpret_cast<const float4*>(b2 + t * D + c4 * 4);
        v.x += bb.x; v.y += bb.y; v.z += bb.z; v.w += bb.w;
        *reinterpret_cast<float4*>(&ys[r][c4 * 4]) = v;
    }
    __syncthreads();
#pragma unroll
    for (int nt = 0; nt < 8; nt++) {
        int col = wn * 64 + nt * 8 + tg * 2, row = wm * 16 + g;
        ys[row][col]         += acc[nt][0];
        ys[row][col + 1]     += acc[nt][1];
        ys[row + 8][col]     += acc[nt][2];
        ys[row + 8][col + 1] += acc[nt][3];
    }
    __syncthreads();

    // LayerNorm over 128; warp owns 8 rows
    float4 gm = *reinterpret_cast<const float4*>(gamma + lane * 4);
    float4 bt = *reinterpret_cast<const float4*>(beta + lane * 4);
    for (int rr = 0; rr < 8; rr++) {
        int r = wid * 8 + rr;
        float4 v = *reinterpret_cast<float4*>(&ys[r][lane * 4]);
        float s = v.x + v.y + v.z + v.w;
#pragma unroll
        for (int o = 16; o > 0; o >>= 1) s += __shfl_xor_sync(~0u, s, o);
        float mu = s * (1.f / 128.f);
        float dx = v.x - mu, dy = v.y - mu, dz = v.z - mu, dw = v.w - mu;
        float q2 = dx * dx + dy * dy + dz * dz + dw * dw;
#pragma unroll
        for (int o = 16; o > 0; o >>= 1) q2 += __shfl_xor_sync(~0u, q2, o);
        float rs = rsqrtf(q2 * (1.f / 128.f) + 1e-5f);
        float4 o4;
        o4.x = dx * rs * gm.x + bt.x;
        o4.y = dy * rs * gm.y + bt.y;
        o4.z = dz * rs * gm.z + bt.z;
        o4.w = dw * rs * gm.w + bt.w;
        *reinterpret_cast<float4*>(
            out + (size_t)(m0 + r) * TD + t * D + lane * 4) = o4;
    }
}

// ============================================================
extern "C" void kernel_launch(void* const* d_in, const int* in_sizes, int n_in,
                              void* d_out, int out_size)
{
    const float* X     = (const float*)d_in[0];
    const float* W1    = (const float*)d_in[1];
    const float* b1    = (const float*)d_in[2];
    const float* W2    = (const float*)d_in[3];
    const float* b2    = (const float*)d_in[4];
    const float* gamma = (const float*)d_in[5];
    const float* beta  = (const float*)d_in[6];
    float* out = (float*)d_out;

    const int smem_attn  = (64 * 132 + 64 * 68) * 4;     // 51,200 B
    const int smem_gemm2 = (64 * 132 + 128 * 136) * 4;   // 103,424 B
    cudaFuncSetAttribute(attn_kernel,
        cudaFuncAttributeMaxDynamicSharedMemorySize, smem_attn);
    cudaFuncSetAttribute(gemm2_ln_kernel,
        cudaFuncAttributeMaxDynamicSharedMemorySize, smem_gemm2);

    gemm1_kernel<<<dim3(64, SPLITK), 256>>>(X, W1);
    reduce_relu_kernel<<<(BATCH * D / 4) / 256, 256>>>(b1);
    attn_kernel<<<BATCH, 256, smem_attn>>>(X);
    gemm2_ln_kernel<<<dim3(64, 64), 256, smem_gemm2>>>(W2, b2, gamma, beta, out);
}

// round 3
// speedup vs baseline: 2.0824x; 1.0122x over previous
#include <cuda_runtime.h>
#include <cstdint>

#define BATCH 4096
#define T 64
#define D 128
#define TD 8192
#define SPLITK 16

// Scratch (__device__ globals per allocation-free rule)
__device__ unsigned g_w1t[(size_t)D * TD];            // W1 tf32, [n][k] interleaved (4MB)
__device__ unsigned g_w2t[(size_t)TD * D];            // W2 tf32, [n][k] interleaved (4MB)
__device__ float    g_hp[(size_t)SPLITK * BATCH * D]; // gemm1 split-K partials (32MB)
__device__ unsigned g_ht[BATCH * D];                  // relu(h+b1), tf32 interleaved (2MB)
__device__ float    g_ypart[(size_t)BATCH * TD];      // X + X_dot (128MB)

// ---------------- helpers ----------------
__device__ __forceinline__ unsigned f2tf32(float f) {
    unsigned r;
    asm("cvt.rna.tf32.f32 %0, %1;" : "=r"(r) : "f"(f));
    return r;
}
// interleave 8 consecutive k-values (v0=c0..c3, v1=c4..c7) as c0,c4,c1,c5,c2,c6,c3,c7
__device__ __forceinline__ void ileave_store(unsigned* dst, float4 v0, float4 v1) {
    uint4 o0, o1;
    o0.x = f2tf32(v0.x); o0.y = f2tf32(v1.x); o0.z = f2tf32(v0.y); o0.w = f2tf32(v1.y);
    o1.x = f2tf32(v0.z); o1.y = f2tf32(v1.z); o1.z = f2tf32(v0.w); o1.w = f2tf32(v1.w);
    *reinterpret_cast<uint4*>(dst)     = o0;
    *reinterpret_cast<uint4*>(dst + 4) = o1;
}
__device__ __forceinline__ void mma_tf32(float* c,
    unsigned a0, unsigned a1, unsigned a2, unsigned a3, unsigned b0, unsigned b1)
{
    asm volatile(
        "mma.sync.aligned.m16n8k8.row.col.f32.tf32.tf32.f32 "
        "{%0,%1,%2,%3}, {%4,%5,%6,%7}, {%8,%9}, {%0,%1,%2,%3};\n"
        : "+f"(c[0]), "+f"(c[1]), "+f"(c[2]), "+f"(c[3])
        : "r"(a0), "r"(a1), "r"(a2), "r"(a3), "r"(b0), "r"(b1));
}
__device__ __forceinline__ void cp16(unsigned* smem_dst, const unsigned* gsrc) {
    unsigned sa = (unsigned)__cvta_generic_to_shared(smem_dst);
    asm volatile("cp.async.cg.shared.global [%0], [%1], 16;\n" :: "r"(sa), "l"(gsrc));
}

// ============================================================
// Prep: W (1M fp32) -> tf32 bits, k-pair interleaved (k contiguous per row)
// ============================================================
__global__ void __launch_bounds__(256) prep_w_kernel(
    const float* __restrict__ W, unsigned* __restrict__ dst)
{
    size_t o = (size_t)(blockIdx.x * 256 + threadIdx.x) * 8;
    float4 v0 = *reinterpret_cast<const float4*>(W + o);
    float4 v1 = *reinterpret_cast<const float4*>(W + o + 4);
    ileave_store(dst + o, v0, v1);
}

// ============================================================
// Kernel 1: split-K GEMM  h_part = X(4096x8192) @ W1^T
// grid (32, 16), 256 thr. M_TILE=128, N=128, K chunk=512, K_TILE=32.
// 2-stage cp.async pipeline for B; register-staged A (needs cvt).
// ============================================================
__global__ void __launch_bounds__(256, 2) gemm1_kernel(const float* __restrict__ X)
{
    extern __shared__ unsigned sm_u[];
    unsigned* Asm = sm_u;                 // 2 stages x [128][40]
    unsigned* Bsm = sm_u + 2 * 128 * 40;  // 2 stages x [128][40]

    const int m0 = blockIdx.x * 128;
    const int k0 = blockIdx.y * 512;
    const int tid = threadIdx.x;
    const int wid = tid >> 5, lane = tid & 31;
    const int g = lane >> 2, tg = lane & 3;
    const int wm = wid & 3, wn = wid >> 2;      // warp tile 32m x 64n

    // fill mappings
    int ar[2], aob[2];
#pragma unroll
    for (int i = 0; i < 2; i++) { int q = tid + i * 256; ar[i] = q & 127; aob[i] = q >> 7; }
    int bn[4], bc[4];
#pragma unroll
    for (int i = 0; i < 4; i++) { int q = tid + i * 256; bn[i] = q >> 3; bc[i] = q & 7; }

    float acc[2][8][4];
#pragma unroll
    for (int m = 0; m < 2; m++)
#pragma unroll
        for (int i = 0; i < 8; i++)
#pragma unroll
            for (int j = 0; j < 4; j++) acc[m][i][j] = 0.f;

    float4 av[2][2];

#define G1_LDA(KK)                                                              \
    {                                                                           \
        _Pragma("unroll")                                                       \
        for (int i = 0; i < 2; i++) {                                           \
            const float* p = X + (size_t)(m0 + ar[i]) * TD + (KK) + aob[i] * 8; \
            av[i][0] = *reinterpret_cast<const float4*>(p);                     \
            av[i][1] = *reinterpret_cast<const float4*>(p + 4);                 \
        }                                                                       \
    }
#define G1_STA(S)                                                               \
    {                                                                           \
        _Pragma("unroll")                                                       \
        for (int i = 0; i < 2; i++)                                             \
            ileave_store(Asm + (S) * 5120 + ar[i] * 40 + aob[i] * 8,            \
                         av[i][0], av[i][1]);                                   \
    }
#define G1_CPB(S, KK)                                                           \
    {                                                                           \
        _Pragma("unroll")                                                       \
        for (int i = 0; i < 4; i++)                                             \
            cp16(Bsm + (S) * 5120 + bn[i] * 40 + bc[i] * 4,                     \
                 g_w1t + (size_t)bn[i] * TD + (KK) + bc[i] * 4);                \
        asm volatile("cp.async.commit_group;\n");                               \
    }

    int kk = k0;
    G1_LDA(kk);
    G1_CPB(0, kk);
    G1_STA(0);
    asm volatile("cp.async.wait_group 0;\n");
    __syncthreads();

    for (int kt = 0; kt < 16; kt++) {
        const int cur = kt & 1, nxt = cur ^ 1;
        if (kt < 15) {
            G1_CPB(nxt, kk + 32);
            G1_LDA(kk + 32);
        }
        const unsigned* A = Asm + cur * 5120;
        const unsigned* B = Bsm + cur * 5120;
#pragma unroll
        for (int ks = 0; ks < 4; ks++) {
            uint2 aL[2], aH[2];
#pragma unroll
            for (int ms = 0; ms < 2; ms++) {
                const unsigned* ap = A + (wm * 32 + ms * 16 + g) * 40 + ks * 8 + 2 * tg;
                aL[ms] = *reinterpret_cast<const uint2*>(ap);
                aH[ms] = *reinterpret_cast<const uint2*>(ap + 8 * 40);
            }
#pragma unroll
            for (int nt = 0; nt < 8; nt++) {
                uint2 b = *reinterpret_cast<const uint2*>(
                    B + (wn * 64 + nt * 8 + g) * 40 + ks * 8 + 2 * tg);
#pragma unroll
                for (int ms = 0; ms < 2; ms++)
                    mma_tf32(acc[ms][nt], aL[ms].x, aH[ms].x, aL[ms].y, aH[ms].y, b.x, b.y);
            }
        }
        if (kt < 15) {
            G1_STA(nxt);
            asm volatile("cp.async.wait_group 0;\n");
        }
        __syncthreads();
        kk += 32;
    }

    float* outp = g_hp + (size_t)blockIdx.y * BATCH * D;
#pragma unroll
    for (int ms = 0; ms < 2; ms++)
#pragma unroll
        for (int nt = 0; nt < 8; nt++) {
            int row = m0 + wm * 32 + ms * 16 + g;
            int col = wn * 64 + nt * 8 + tg * 2;
            *reinterpret_cast<float2*>(outp + (size_t)row * D + col) =
                make_float2(acc[ms][nt][0], acc[ms][nt][1]);
            *reinterpret_cast<float2*>(outp + (size_t)(row + 8) * D + col) =
                make_float2(acc[ms][nt][2], acc[ms][nt][3]);
        }
}

// ============================================================
// Kernel 1b: g_ht = tf32_ileave( relu( sum_p g_hp[p] + b1 ) )
// one thread per 8-element octet
// ============================================================
__global__ void __launch_bounds__(256) reduce_relu_kernel(const float* __restrict__ b1)
{
    const int o = blockIdx.x * 256 + threadIdx.x;   // 65536 octets
    const int row = o >> 4, ob = o & 15;
    const size_t base = (size_t)row * D + ob * 8;
    float4 s0 = *reinterpret_cast<const float4*>(b1 + ob * 8);
    float4 s1 = *reinterpret_cast<const float4*>(b1 + ob * 8 + 4);
#pragma unroll
    for (int p = 0; p < SPLITK; p++) {
        const float* hp = g_hp + (size_t)p * BATCH * D + base;
        float4 v0 = *reinterpret_cast<const float4*>(hp);
        float4 v1 = *reinterpret_cast<const float4*>(hp + 4);
        s0.x += v0.x; s0.y += v0.y; s0.z += v0.z; s0.w += v0.w;
        s1.x += v1.x; s1.y += v1.y; s1.z += v1.z; s1.w += v1.w;
    }
    s0.x = fmaxf(s0.x, 0.f); s0.y = fmaxf(s0.y, 0.f);
    s0.z = fmaxf(s0.z, 0.f); s0.w = fmaxf(s0.w, 0.f);
    s1.x = fmaxf(s1.x, 0.f); s1.y = fmaxf(s1.y, 0.f);
    s1.z = fmaxf(s1.z, 0.f); s1.w = fmaxf(s1.w, 0.f);
    ileave_store(g_ht + base, s0, s1);
}

// ============================================================
// Kernel 2: per-batch attention: scores -> softmax -> attn@X -> +X
// grid 4096, 256 thr. Xt[64][136] tf32 interleaved; Ss[64][72].
// ============================================================
__global__ void __launch_bounds__(256) attn_kernel(const float* __restrict__ X)
{
    extern __shared__ unsigned sm_u[];
    unsigned (*Xt)[136] = reinterpret_cast<unsigned(*)[136]>(sm_u);
    float    (*Ss)[72]  = reinterpret_cast<float(*)[72]>(sm_u + 64 * 136);
    unsigned (*Ssu)[72] = reinterpret_cast<unsigned(*)[72]>(sm_u + 64 * 136);

    const int b = blockIdx.x;
    const float* Xb = X + (size_t)b * TD;
    const int tid = threadIdx.x, wid = tid >> 5, lane = tid & 31;
    const int g = lane >> 2, tg = lane & 3;
    const int wm = wid & 3, wn = wid >> 2;

    // load + cvt + interleave X_b (64x128): 4 octets/thread
#pragma unroll
    for (int i = 0; i < 4; i++) {
        int q = tid + i * 256;
        int r = q >> 4, ob = q & 15;
        const float* p = Xb + r * D + ob * 8;
        float4 v0 = *reinterpret_cast<const float4*>(p);
        float4 v1 = *reinterpret_cast<const float4*>(p + 4);
        ileave_store(&Xt[r][ob * 8], v0, v1);
    }
    __syncthreads();

    // scores = X X^T * scale; warp tile 16m x 32n
    {
        float acc[4][4];
#pragma unroll
        for (int i = 0; i < 4; i++)
#pragma unroll
            for (int j = 0; j < 4; j++) acc[i][j] = 0.f;
#pragma unroll
        for (int ks = 0; ks < 16; ks++) {
            const unsigned* ap = &Xt[wm * 16 + g][ks * 8 + 2 * tg];
            uint2 aL = *reinterpret_cast<const uint2*>(ap);
            uint2 aH = *reinterpret_cast<const uint2*>(ap + 8 * 136);
#pragma unroll
            for (int nt = 0; nt < 4; nt++) {
                uint2 bb = *reinterpret_cast<const uint2*>(
                    &Xt[wn * 32 + nt * 8 + g][ks * 8 + 2 * tg]);
                mma_tf32(acc[nt], aL.x, aH.x, aL.y, aH.y, bb.x, bb.y);
            }
        }
        const float scale = 0.0883883476483184f;   // 128^-0.5
#pragma unroll
        for (int nt = 0; nt < 4; nt++) {
            int col = wn * 32 + nt * 8 + tg * 2, row = wm * 16 + g;
            *reinterpret_cast<float2*>(&Ss[row][col]) =
                make_float2(acc[nt][0] * scale, acc[nt][1] * scale);
            *reinterpret_cast<float2*>(&Ss[row + 8][col]) =
                make_float2(acc[nt][2] * scale, acc[nt][3] * scale);
        }
    }
    __syncthreads();

    // softmax per row; write tf32 probs at interleaved positions
    for (int rr = 0; rr < 8; rr++) {
        int r = wid * 8 + rr;
        float v0 = Ss[r][lane * 2], v1 = Ss[r][lane * 2 + 1];
        float m = fmaxf(v0, v1);
#pragma unroll
        for (int o = 16; o > 0; o >>= 1) m = fmaxf(m, __shfl_xor_sync(~0u, m, o));
        float e0 = __expf(v0 - m), e1 = __expf(v1 - m);
        float s = e0 + e1;
#pragma unroll
        for (int o = 16; o > 0; o >>= 1) s += __shfl_xor_sync(~0u, s, o);
        float inv = 1.f / s;
        __syncwarp();
        int c0 = lane * 2, c1 = lane * 2 + 1;
        int p0 = (c0 & ~7) | ((c0 & 3) << 1) | ((c0 >> 2) & 1);
        int p1 = (c1 & ~7) | ((c1 & 3) << 1) | ((c1 >> 2) & 1);
        Ssu[r][p0] = f2tf32(e0 * inv);
        Ssu[r][p1] = f2tf32(e1 * inv);
    }
    __syncthreads();

    // X_dot = attn @ X (64x128, K=64); warp tile 16m x 64n
    float acc[8][4];
#pragma unroll
    for (int i = 0; i < 8; i++)
#pragma unroll
        for (int j = 0; j < 4; j++) acc[i][j] = 0.f;
#pragma unroll
    for (int ks = 0; ks < 8; ks++) {
        const unsigned* ap = &Ssu[wm * 16 + g][ks * 8 + 2 * tg];
        uint2 aL = *reinterpret_cast<const uint2*>(ap);
        uint2 aH = *reinterpret_cast<const uint2*>(ap + 8 * 72);
#pragma unroll
        for (int nt = 0; nt < 8; nt++) {
            unsigned b0 = Xt[ks * 8 + tg    ][wn * 64 + nt * 8 + g];
            unsigned b1 = Xt[ks * 8 + tg + 4][wn * 64 + nt * 8 + g];
            mma_tf32(acc[nt], aL.x, aH.x, aL.y, aH.y, b0, b1);
        }
    }
    // epilogue: B's n-dim was interleaved -> output cols are (tg, tg+4) within block
    float* yp = g_ypart + (size_t)b * TD;
#pragma unroll
    for (int nt = 0; nt < 8; nt++) {
        int colb = wn * 64 + nt * 8;
        int row = wm * 16 + g;
        yp[row * D + colb + tg]           = acc[nt][0] + Xb[row * D + colb + tg];
        yp[row * D + colb + tg + 4]       = acc[nt][1] + Xb[row * D + colb + tg + 4];
        yp[(row + 8) * D + colb + tg]     = acc[nt][2] + Xb[(row + 8) * D + colb + tg];
        yp[(row + 8) * D + colb + tg + 4] = acc[nt][3] + Xb[(row + 8) * D + colb + tg + 4];
    }
}

// ============================================================
// Kernel 3: out = LN( ypart + b2 + g_ht @ W2^T ) * gamma + beta
// grid (64, 64), 256 thr. M_TILE=64, N=128, K=128 in 2 chunks of 64.
// A[64][136] full-K (copy of g_ht); B[128][72] per chunk (copy of g_w2t).
// ============================================================
__global__ void __launch_bounds__(256) gemm2_ln_kernel(
    const float* __restrict__ b2, const float* __restrict__ gamma,
    const float* __restrict__ beta, float* __restrict__ out)
{
    extern __shared__ unsigned sm_u[];
    unsigned* A = sm_u;                 // [64][136]
    unsigned* B = sm_u + 64 * 136;      // [128][72]

    const int m0 = blockIdx.x * 64;
    const int t  = blockIdx.y;
    const int tid = threadIdx.x, wid = tid >> 5, lane = tid & 31;
    const int g = lane >> 2, tg = lane & 3;
    const int wm = wid & 3, wn = wid >> 2;     // warp tile 16m x 64n

    // A fill: straight uint4 copy of pre-interleaved tf32 relu(h)
#pragma unroll
    for (int i = 0; i < 8; i++) {
        int q = tid + i * 256;
        int r = q >> 5, c = q & 31;
        *reinterpret_cast<uint4*>(A + r * 136 + c * 4) =
            *reinterpret_cast<const uint4*>(g_ht + (size_t)(m0 + r) * D + c * 4);
    }

    float acc[8][4];
#pragma unroll
    for (int i = 0; i < 8; i++)
#pragma unroll
        for (int j = 0; j < 4; j++) acc[i][j] = 0.f;

    for (int kc = 0; kc < 2; kc++) {
        // B fill: straight uint4 copy of pre-interleaved tf32 W2 chunk
#pragma unroll
        for (int i = 0; i < 8; i++) {
            int q = tid + i * 256;
            int n = q >> 4, c = q & 15;
            *reinterpret_cast<uint4*>(B + n * 72 + c * 4) =
                *reinterpret_cast<const uint4*>(
                    g_w2t + (size_t)(t * D + n) * D + kc * 64 + c * 4);
        }
        __syncthreads();
#pragma unroll
        for (int ks = 0; ks < 8; ks++) {
            const unsigned* ap = A + (wm * 16 + g) * 136 + kc * 64 + ks * 8 + 2 * tg;
            uint2 aL = *reinterpret_cast<const uint2*>(ap);
            uint2 aH = *reinterpret_cast<const uint2*>(ap + 8 * 136);
#pragma unroll
            for (int nt = 0; nt < 8; nt++) {
                uint2 bb = *reinterpret_cast<const uint2*>(
                    B + (wn * 64 + nt * 8 + g) * 72 + ks * 8 + 2 * tg);
                mma_tf32(acc[nt], aL.x, aH.x, aL.y, aH.y, bb.x, bb.y);
            }
        }
        __syncthreads();
    }

    // epilogue: ys aliases A region (fp32)
    float (*ys)[136] = reinterpret_cast<float(*)[136]>(A);
#pragma unroll
    for (int i = 0; i < 8; i++) {
        int q = tid + i * 256;
        int r = q >> 5, c = q & 31;
        float4 v  = *reinterpret_cast<const float4*>(
            g_ypart + (size_t)(m0 + r) * TD + t * D + c * 4);
        float4 bb = *reinterpret_cast<const float4*>(b2 + t * D + c * 4);
        v.x += bb.x; v.y += bb.y; v.z += bb.z; v.w += bb.w;
        *reinterpret_cast<float4*>(&ys[r][c * 4]) = v;
    }
    __syncthreads();
#pragma unroll
    for (int nt = 0; nt < 8; nt++) {
        int col = wn * 64 + nt * 8 + tg * 2, row = wm * 16 + g;
        ys[row][col]         += acc[nt][0];
        ys[row][col + 1]     += acc[nt][1];
        ys[row + 8][col]     += acc[nt][2];
        ys[row + 8][col + 1] += acc[nt][3];
    }
    __syncthreads();

    // LayerNorm; warp owns 8 rows
    float4 gm = *reinterpret_cast<const float4*>(gamma + lane * 4);
    float4 bt = *reinterpret_cast<const float4*>(beta + lane * 4);
    for (int rr = 0; rr < 8; rr++) {
        int r = wid * 8 + rr;
        float4 v = *reinterpret_cast<float4*>(&ys[r][lane * 4]);
        float s = v.x + v.y + v.z + v.w;
#pragma unroll
        for (int o = 16; o > 0; o >>= 1) s += __shfl_xor_sync(~0u, s, o);
        float mu = s * (1.f / 128.f);
        float dx = v.x - mu, dy = v.y - mu, dz = v.z - mu, dw = v.w - mu;
        float q2 = dx * dx + dy * dy + dz * dz + dw * dw;
#pragma unroll
        for (int o = 16; o > 0; o >>= 1) q2 += __shfl_xor_sync(~0u, q2, o);
        float rs = rsqrtf(q2 * (1.f / 128.f) + 1e-5f);
        float4 o4;
        o4.x = dx * rs * gm.x + bt.x;
        o4.y = dy * rs * gm.y + bt.y;
        o4.z = dz * rs * gm.z + bt.z;
        o4.w = dw * rs * gm.w + bt.w;
        *reinterpret_cast<float4*>(
            out + (size_t)(m0 + r) * TD + t * D + lane * 4) = o4;
    }
}

// ============================================================
extern "C" void kernel_launch(void* const* d_in, const int* in_sizes, int n_in,
                              void* d_out, int out_size)
{
    const float* X     = (const float*)d_in[0];
    const float* W1    = (const float*)d_in[1];
    const float* b1    = (const float*)d_in[2];
    const float* W2    = (const float*)d_in[3];
    const float* b2    = (const float*)d_in[4];
    const float* gamma = (const float*)d_in[5];
    const float* beta  = (const float*)d_in[6];
    float* out = (float*)d_out;

    unsigned* w1t; cudaGetSymbolAddress((void**)&w1t, g_w1t);
    unsigned* w2t; cudaGetSymbolAddress((void**)&w2t, g_w2t);

    const int smem_g1   = 2 * (128 * 40) * 2 * 4;          // 81,920 B
    const int smem_attn = (64 * 136 + 64 * 72) * 4;        // 53,248 B
    const int smem_g2   = (64 * 136 + 128 * 72) * 4;       // 71,680 B
    cudaFuncSetAttribute(gemm1_kernel,
        cudaFuncAttributeMaxDynamicSharedMemorySize, smem_g1);
    cudaFuncSetAttribute(attn_kernel,
        cudaFuncAttributeMaxDynamicSharedMemorySize, smem_attn);
    cudaFuncSetAttribute(gemm2_ln_kernel,
        cudaFuncAttributeMaxDynamicSharedMemorySize, smem_g2);

    prep_w_kernel<<<512, 256>>>(W1, w1t);
    prep_w_kernel<<<512, 256>>>(W2, w2t);
    gemm1_kernel<<<dim3(32, SPLITK), 256, smem_g1>>>(X);
    reduce_relu_kernel<<<256, 256>>>(b1);
    attn_kernel<<<BATCH, 256, smem_attn>>>(X);
    gemm2_ln_kernel<<<dim3(64, 64), 256, smem_g2>>>(b2, gamma, beta, out);
}

// round 5
// speedup vs baseline: 3.4411x; 1.6525x over previous
#include <cuda_runtime.h>
#include <cuda_fp16.h>
#include <cstdint>

#define BATCH 4096
#define T 64
#define D 128
#define TD 8192
#define SPLITK 8

// Scratch (__device__ globals per allocation-free rule)
__device__ __half g_w1h[(size_t)D * TD];             // W1 fp16, [n][k] (2MB)
__device__ __half g_w2h[(size_t)TD * D];             // W2 fp16, [n][k] (2MB)
__device__ __half g_hp[(size_t)SPLITK * BATCH * D];  // gemm1 partials fp16 (8MB)
__device__ __half g_ht[(size_t)BATCH * D];           // relu(h+b1) fp16 (1MB)
__device__ __half g_ypart[(size_t)BATCH * TD];       // X + X_dot fp16 (64MB)

// ---------------- helpers ----------------
__device__ __forceinline__ unsigned pack2(float lo, float hi) {
    unsigned r;
    asm("cvt.rn.f16x2.f32 %0, %1, %2;" : "=r"(r) : "f"(hi), "f"(lo));
    return r;
}
__device__ __forceinline__ uint4 pack8(float4 v0, float4 v1) {
    uint4 u;
    u.x = pack2(v0.x, v0.y); u.y = pack2(v0.z, v0.w);
    u.z = pack2(v1.x, v1.y); u.w = pack2(v1.z, v1.w);
    return u;
}
__device__ __forceinline__ void mma_f16(float* c,
    unsigned a0, unsigned a1, unsigned a2, unsigned a3, unsigned b0, unsigned b1)
{
    asm volatile(
        "mma.sync.aligned.m16n8k16.row.col.f32.f16.f16.f32 "
        "{%0,%1,%2,%3}, {%4,%5,%6,%7}, {%8,%9}, {%0,%1,%2,%3};\n"
        : "+f"(c[0]), "+f"(c[1]), "+f"(c[2]), "+f"(c[3])
        : "r"(a0), "r"(a1), "r"(a2), "r"(a3), "r"(b0), "r"(b1));
}
__device__ __forceinline__ void cp16(__half* smem_dst, const __half* gsrc) {
    unsigned sa = (unsigned)__cvta_generic_to_shared(smem_dst);
    asm volatile("cp.async.cg.shared.global [%0], [%1], 16;\n" :: "r"(sa), "l"(gsrc));
}

// ============================================================
// Prep: W1 (1M) and W2 (1M) fp32 -> fp16, layouts already [n][k]
// ============================================================
__global__ void __launch_bounds__(256) prep_w_kernel(
    const float* __restrict__ W1, const float* __restrict__ W2)
{
    size_t o = (size_t)(blockIdx.x * 256 + threadIdx.x) * 8;
    const size_t NW = (size_t)D * TD;
    const float* src = (o < NW) ? (W1 + o) : (W2 + (o - NW));
    __half* dst = (o < NW) ? (g_w1h + o) : (g_w2h + (o - NW));
    float4 v0 = *reinterpret_cast<const float4*>(src);
    float4 v1 = *reinterpret_cast<const float4*>(src + 4);
    *reinterpret_cast<uint4*>(dst) = pack8(v0, v1);
}

// ============================================================
// Kernel 1: split-K GEMM  h_part = X(4096x8192) @ W1^T (fp16 mma)
// grid (32, 8), 256 thr. M_TILE=128, N=128, K chunk=1024, K_TILE=64.
// 2-stage pipeline: cp.async for B, register-staged cvt for A.
// ============================================================
__global__ void __launch_bounds__(256, 2) gemm1_kernel(const float* __restrict__ X)
{
    extern __shared__ __half smh[];
    __half* Asm = smh;                 // 2 stages x 9216 halves (128 x 72)
    __half* Bsm = smh + 2 * 9216;

    const int m0 = blockIdx.x * 128;
    const int k0 = blockIdx.y * 1024;
    const int tid = threadIdx.x;
    const int wid = tid >> 5, lane = tid & 31;
    const int g = lane >> 2, tg = lane & 3;
    const int wm = wid & 3, wn = wid >> 2;     // warp tile 32m x 64n

    int r4[4], o4[4];
#pragma unroll
    for (int i = 0; i < 4; i++) { int q = tid + i * 256; r4[i] = q >> 3; o4[i] = q & 7; }

    float acc[2][8][4];
#pragma unroll
    for (int m = 0; m < 2; m++)
#pragma unroll
        for (int i = 0; i < 8; i++)
#pragma unroll
            for (int j = 0; j < 4; j++) acc[m][i][j] = 0.f;

    float4 av[4][2];

#define G1_LDA(KK)                                                               \
    {                                                                            \
        _Pragma("unroll")                                                        \
        for (int i = 0; i < 4; i++) {                                            \
            const float* p = X + (size_t)(m0 + r4[i]) * TD + (KK) + o4[i] * 8;   \
            av[i][0] = *reinterpret_cast<const float4*>(p);                      \
            av[i][1] = *reinterpret_cast<const float4*>(p + 4);                  \
        }                                                                        \
    }
#define G1_STA(S)                                                                \
    {                                                                            \
        _Pragma("unroll")                                                        \
        for (int i = 0; i < 4; i++)                                              \
            *reinterpret_cast<uint4*>(Asm + (S) * 9216 + r4[i] * 72 + o4[i] * 8) \
                = pack8(av[i][0], av[i][1]);                                     \
    }
#define G1_CPB(S, KK)                                                            \
    {                                                                            \
        _Pragma("unroll")                                                        \
        for (int i = 0; i < 4; i++)                                              \
            cp16(Bsm + (S) * 9216 + r4[i] * 72 + o4[i] * 8,                      \
                 g_w1h + (size_t)r4[i] * TD + (KK) + o4[i] * 8);                 \
        asm volatile("cp.async.commit_group;\n");                                \
    }

    int kk = k0;
    G1_LDA(kk);
    G1_CPB(0, kk);
    G1_STA(0);
    asm volatile("cp.async.wait_group 0;\n");
    __syncthreads();

    for (int kt = 0; kt < 16; kt++) {
        const int cur = kt & 1, nxt = cur ^ 1;
        if (kt < 15) {
            G1_CPB(nxt, kk + 64);
            G1_LDA(kk + 64);
        }
        const __half* A = Asm + cur * 9216;
        const __half* B = Bsm + cur * 9216;
#pragma unroll
        for (int ks = 0; ks < 4; ks++) {
            unsigned a0[2], a1[2], a2[2], a3[2];
#pragma unroll
            for (int ms = 0; ms < 2; ms++) {
                const __half* ap = A + (wm * 32 + ms * 16 + g) * 72 + ks * 16 + 2 * tg;
                a0[ms] = *reinterpret_cast<const unsigned*>(ap);
                a2[ms] = *reinterpret_cast<const unsigned*>(ap + 8);
                a1[ms] = *reinterpret_cast<const unsigned*>(ap + 8 * 72);
                a3[ms] = *reinterpret_cast<const unsigned*>(ap + 8 * 72 + 8);
            }
#pragma unroll
            for (int nt = 0; nt < 8; nt++) {
                const __half* bp = B + (wn * 64 + nt * 8 + g) * 72 + ks * 16 + 2 * tg;
                unsigned b0 = *reinterpret_cast<const unsigned*>(bp);
                unsigned b1 = *reinterpret_cast<const unsigned*>(bp + 8);
#pragma unroll
                for (int ms = 0; ms < 2; ms++)
                    mma_f16(acc[ms][nt], a0[ms], a1[ms], a2[ms], a3[ms], b0, b1);
            }
        }
        if (kt < 15) {
            G1_STA(nxt);
            asm volatile("cp.async.wait_group 0;\n");
        }
        __syncthreads();
        kk += 64;
    }

    __half* outp = g_hp + (size_t)blockIdx.y * BATCH * D;
#pragma unroll
    for (int ms = 0; ms < 2; ms++)
#pragma unroll
        for (int nt = 0; nt < 8; nt++) {
            int row = m0 + wm * 32 + ms * 16 + g;
            int col = wn * 64 + nt * 8 + 2 * tg;
            *reinterpret_cast<unsigned*>(outp + (size_t)row * D + col) =
                pack2(acc[ms][nt][0], acc[ms][nt][1]);
            *reinterpret_cast<unsigned*>(outp + (size_t)(row + 8) * D + col) =
                pack2(acc[ms][nt][2], acc[ms][nt][3]);
        }
}

// ============================================================
// Kernel 1b: g_ht = fp16( relu( sum_p g_hp[p] + b1 ) )
// ============================================================
__global__ void __launch_bounds__(256) reduce_relu_kernel(const float* __restrict__ b1)
{
    const int o = blockIdx.x * 256 + threadIdx.x;   // 65536 octets
    const size_t base = (size_t)o * 8;
    const int col = (o & 15) * 8;
    float4 s0 = *reinterpret_cast<const float4*>(b1 + col);
    float4 s1 = *reinterpret_cast<const float4*>(b1 + col + 4);
#pragma unroll
    for (int p = 0; p < SPLITK; p++) {
        uint4 u = *reinterpret_cast<const uint4*>(g_hp + (size_t)p * BATCH * D + base);
        float2 f0 = __half22float2(*reinterpret_cast<__half2*>(&u.x));
        float2 f1 = __half22float2(*reinterpret_cast<__half2*>(&u.y));
        float2 f2 = __half22float2(*reinterpret_cast<__half2*>(&u.z));
        float2 f3 = __half22float2(*reinterpret_cast<__half2*>(&u.w));
        s0.x += f0.x; s0.y += f0.y; s0.z += f1.x; s0.w += f1.y;
        s1.x += f2.x; s1.y += f2.y; s1.z += f3.x; s1.w += f3.y;
    }
    s0.x = fmaxf(s0.x, 0.f); s0.y = fmaxf(s0.y, 0.f);
    s0.z = fmaxf(s0.z, 0.f); s0.w = fmaxf(s0.w, 0.f);
    s1.x = fmaxf(s1.x, 0.f); s1.y = fmaxf(s1.y, 0.f);
    s1.z = fmaxf(s1.z, 0.f); s1.w = fmaxf(s1.w, 0.f);
    *reinterpret_cast<uint4*>(g_ht + base) = pack8(s0, s1);
}

// ============================================================
// Kernel 2: per-batch attention (fp16 mma)
// smem: Xn[64][136]h, Xtr[128][72]h, Ss[64][76]f (Ps aliases Ss, stride 152 h)
// ============================================================
__global__ void __launch_bounds__(256, 3) attn_kernel(const float* __restrict__ X)
{
    extern __shared__ __half smh[];
    __half* Xn  = smh;                  // 64 x 136
    __half* Xtr = smh + 8704;           // 128 x 72
    float*  Ssf = reinterpret_cast<float*>(smh + 8704 + 9216);   // 64 x 76 fp32
    __half* Ps  = reinterpret_cast<__half*>(Ssf);                // stride 152 halves

    const int b = blockIdx.x;
    const float* Xb = X + (size_t)b * TD;
    const int tid = threadIdx.x, wid = tid >> 5, lane = tid & 31;
    const int g = lane >> 2, tg = lane & 3;
    const int wm = wid & 3, wn = wid >> 2;

    // fill Xn (convert fp32 -> fp16)
#pragma unroll
    for (int i = 0; i < 4; i++) {
        int q = tid + i * 256;
        int r = q >> 4, o = q & 15;
        const float* p = Xb + r * D + o * 8;
        float4 v0 = *reinterpret_cast<const float4*>(p);
        float4 v1 = *reinterpret_cast<const float4*>(p + 4);
        *reinterpret_cast<uint4*>(Xn + r * 136 + o * 8) = pack8(v0, v1);
    }
    __syncthreads();

    // fill Xtr[d][s] = Xn[s][d] (each thread: one d-row half, 32 s values)
    {
        const int d = tid >> 1, s0 = (tid & 1) * 32;
        __align__(16) __half tmp[32];
#pragma unroll
        for (int s = 0; s < 32; s++) tmp[s] = Xn[(s0 + s) * 136 + d];
#pragma unroll
        for (int c = 0; c < 4; c++)
            *reinterpret_cast<uint4*>(Xtr + d * 72 + s0 + c * 8) =
                *reinterpret_cast<uint4*>(tmp + c * 8);
    }
    // QK: scores = X X^T * scale; warp tile 16m x 32n (reads only Xn)
    {
        float acc[4][4];
#pragma unroll
        for (int i = 0; i < 4; i++)
#pragma unroll
            for (int j = 0; j < 4; j++) acc[i][j] = 0.f;
#pragma unroll
        for (int ks = 0; ks < 8; ks++) {
            const __half* ap = Xn + (wm * 16 + g) * 136 + ks * 16 + 2 * tg;
            unsigned a0 = *reinterpret_cast<const unsigned*>(ap);
            unsigned a2 = *reinterpret_cast<const unsigned*>(ap + 8);
            unsigned a1 = *reinterpret_cast<const unsigned*>(ap + 8 * 136);
            unsigned a3 = *reinterpret_cast<const unsigned*>(ap + 8 * 136 + 8);
#pragma unroll
            for (int nt = 0; nt < 4; nt++) {
                const __half* bp = Xn + (wn * 32 + nt * 8 + g) * 136 + ks * 16 + 2 * tg;
                unsigned b0 = *reinterpret_cast<const unsigned*>(bp);
                unsigned b1 = *reinterpret_cast<const unsigned*>(bp + 8);
                mma_f16(acc[nt], a0, a1, a2, a3, b0, b1);
            }
        }
        const float scale = 0.0883883476483184f;   // 128^-0.5
#pragma unroll
        for (int nt = 0; nt < 4; nt++) {
            int col = wn * 32 + nt * 8 + 2 * tg, row = wm * 16 + g;
            *reinterpret_cast<float2*>(Ssf + row * 76 + col) =
                make_float2(acc[nt][0] * scale, acc[nt][1] * scale);
            *reinterpret_cast<float2*>(Ssf + (row + 8) * 76 + col) =
                make_float2(acc[nt][2] * scale, acc[nt][3] * scale);
        }
    }
    __syncthreads();

    // softmax per row; write fp16 probs in place (Ps aliases Ss rows)
    for (int rr = 0; rr < 8; rr++) {
        int r = wid * 8 + rr;
        float v0 = Ssf[r * 76 + lane * 2], v1 = Ssf[r * 76 + lane * 2 + 1];
        float m = fmaxf(v0, v1);
#pragma unroll
        for (int o = 16; o > 0; o >>= 1) m = fmaxf(m, __shfl_xor_sync(~0u, m, o));
        float e0 = __expf(v0 - m), e1 = __expf(v1 - m);
        float s = e0 + e1;
#pragma unroll
        for (int o = 16; o > 0; o >>= 1) s += __shfl_xor_sync(~0u, s, o);
        float inv = 1.f / s;
        *reinterpret_cast<unsigned*>(Ps + r * 152 + lane * 2) = pack2(e0 * inv, e1 * inv);
    }
    __syncthreads();

    // PV: X_dot = attn @ X; warp tile 16m x 64n, K=64 tokens
    float acc[8][4];
#pragma unroll
    for (int i = 0; i < 8; i++)
#pragma unroll
        for (int j = 0; j < 4; j++) acc[i][j] = 0.f;
#pragma unroll
    for (int ks = 0; ks < 4; ks++) {
        const __half* ap = Ps + (wm * 16 + g) * 152 + ks * 16 + 2 * tg;
        unsigned a0 = *reinterpret_cast<const unsigned*>(ap);
        unsigned a2 = *reinterpret_cast<const unsigned*>(ap + 8);
        unsigned a1 = *reinterpret_cast<const unsigned*>(ap + 8 * 152);
        unsigned a3 = *reinterpret_cast<const unsigned*>(ap + 8 * 152 + 8);
#pragma unroll
        for (int nt = 0; nt < 8; nt++) {
            const __half* bp = Xtr + (wn * 64 + nt * 8 + g) * 72 + ks * 16 + 2 * tg;
            unsigned b0 = *reinterpret_cast<const unsigned*>(bp);
            unsigned b1 = *reinterpret_cast<const unsigned*>(bp + 8);
            mma_f16(acc[nt], a0, a1, a2, a3, b0, b1);
        }
    }
    // epilogue: + X (from smem fp16), write ypart fp16
    __half* yp = g_ypart + (size_t)b * TD;
#pragma unroll
    for (int nt = 0; nt < 8; nt++) {
        int col = wn * 64 + nt * 8 + 2 * tg;
        int row = wm * 16 + g;
        float2 x0 = __half22float2(*reinterpret_cast<const __half2*>(Xn + row * 136 + col));
        float2 x1 = __half22float2(*reinterpret_cast<const __half2*>(Xn + (row + 8) * 136 + col));
        *reinterpret_cast<unsigned*>(yp + row * D + col) =
            pack2(acc[nt][0] + x0.x, acc[nt][1] + x0.y);
        *reinterpret_cast<unsigned*>(yp + (row + 8) * D + col) =
            pack2(acc[nt][2] + x1.x, acc[nt][3] + x1.y);
    }
}

// ============================================================
// Kernel 3: out = LN( ypart + b2 + g_ht @ W2^T ) * gamma + beta (fp16 mma)
// grid (64, 64), 256 thr. M_TILE=64, N=128, K=128 single shot.
// smem: As[64][136]h + Bs[128][136]h; ys fp32 [64][132] aliases Bs.
// ============================================================
__global__ void __launch_bounds__(256, 3) gemm2_ln_kernel(
    const float* __restrict__ b2, const float* __restrict__ gamma,
    const float* __restrict__ beta, float* __restrict__ out)
{
    extern __shared__ __half smh[];
    __half* As = smh;                   // 64 x 136
    __half* Bs = smh + 8704;            // 128 x 136
    float*  ys = reinterpret_cast<float*>(Bs);   // 64 x 132 fp32 (after mma)

    const int m0 = blockIdx.x * 64;
    const int t  = blockIdx.y;
    const int tid = threadIdx.x, wid = tid >> 5, lane = tid & 31;
    const int g = lane >> 2, tg = lane & 3;
    const int wm = wid & 3, wn = wid >> 2;      // warp tile 16m x 64n

    // A fill: 64 rows x 128 halves = 1024 uint4 (FIXED coverage: 4 iters, 16 octets/row)
#pragma unroll
    for (int i = 0; i < 4; i++) {
        int q = tid + i * 256;
        int r = q >> 4, o = q & 15;
        *reinterpret_cast<uint4*>(As + r * 136 + o * 8) =
            *reinterpret_cast<const uint4*>(g_ht + (size_t)(m0 + r) * D + o * 8);
    }
    // B fill: cp.async of fp16 W2 rows (128 x 128)
#pragma unroll
    for (int i = 0; i < 8; i++) {
        int q = tid + i * 256;
        int n = q >> 4, o = q & 15;
        cp16(Bs + n * 136 + o * 8,
             g_w2h + (size_t)(t * D + n) * D + o * 8);
    }
    asm volatile("cp.async.commit_group;\n");
    asm volatile("cp.async.wait_group 0;\n");
    __syncthreads();

    float acc[8][4];
#pragma unroll
    for (int i = 0; i < 8; i++)
#pragma unroll
        for (int j = 0; j < 4; j++) acc[i][j] = 0.f;
#pragma unroll
    for (int ks = 0; ks < 8; ks++) {
        const __half* ap = As + (wm * 16 + g) * 136 + ks * 16 + 2 * tg;
        unsigned a0 = *reinterpret_cast<const unsigned*>(ap);
        unsigned a2 = *reinterpret_cast<const unsigned*>(ap + 8);
        unsigned a1 = *reinterpret_cast<const unsigned*>(ap + 8 * 136);
        unsigned a3 = *reinterpret_cast<const unsigned*>(ap + 8 * 136 + 8);
#pragma unroll
        for (int nt = 0; nt < 8; nt++) {
            const __half* bp = Bs + (wn * 64 + nt * 8 + g) * 136 + ks * 16 + 2 * tg;
            unsigned b0 = *reinterpret_cast<const unsigned*>(bp);
            unsigned b1 = *reinterpret_cast<const unsigned*>(bp + 8);
            mma_f16(acc[nt], a0, a1, a2, a3, b0, b1);
        }
    }
    __syncthreads();     // mma reads done; Bs region becomes ys

    // ys = ypart + b2
#pragma unroll
    for (int i = 0; i < 4; i++) {
        int q = tid + i * 256;
        int r = q >> 4, o = q & 15;
        uint4 u = *reinterpret_cast<const uint4*>(
            g_ypart + (size_t)(m0 + r) * TD + t * D + o * 8);
        float4 bb0 = *reinterpret_cast<const float4*>(b2 + t * D + o * 8);
        float4 bb1 = *reinterpret_cast<const float4*>(b2 + t * D + o * 8 + 4);
        float2 f0 = __half22float2(*reinterpret_cast<__half2*>(&u.x));
        float2 f1 = __half22float2(*reinterpret_cast<__half2*>(&u.y));
        float2 f2 = __half22float2(*reinterpret_cast<__half2*>(&u.z));
        float2 f3 = __half22float2(*reinterpret_cast<__half2*>(&u.w));
        float4 w0 = make_float4(f0.x + bb0.x, f0.y + bb0.y, f1.x + bb0.z, f1.y + bb0.w);
        float4 w1 = make_float4(f2.x + bb1.x, f2.y + bb1.y, f3.x + bb1.z, f3.y + bb1.w);
        *reinterpret_cast<float4*>(ys + r * 132 + o * 8)     = w0;
        *reinterpret_cast<float4*>(ys + r * 132 + o * 8 + 4) = w1;
    }
    __syncthreads();
#pragma unroll
    for (int nt = 0; nt < 8; nt++) {
        int col = wn * 64 + nt * 8 + 2 * tg, row = wm * 16 + g;
        ys[row * 132 + col]           += acc[nt][0];
        ys[row * 132 + col + 1]       += acc[nt][1];
        ys[(row + 8) * 132 + col]     += acc[nt][2];
        ys[(row + 8) * 132 + col + 1] += acc[nt][3];
    }
    __syncthreads();

    // LayerNorm; warp owns 8 rows
    float4 gm = *reinterpret_cast<const float4*>(gamma + lane * 4);
    float4 bt = *reinterpret_cast<const float4*>(beta + lane * 4);
    for (int rr = 0; rr < 8; rr++) {
        int r = wid * 8 + rr;
        float4 v = *reinterpret_cast<float4*>(ys + r * 132 + lane * 4);
        float s = v.x + v.y + v.z + v.w;
#pragma unroll
        for (int o = 16; o > 0; o >>= 1) s += __shfl_xor_sync(~0u, s, o);
        float mu = s * (1.f / 128.f);
        float dx = v.x - mu, dy = v.y - mu, dz = v.z - mu, dw = v.w - mu;
        float q2 = dx * dx + dy * dy + dz * dz + dw * dw;
#pragma unroll
        for (int o = 16; o > 0; o >>= 1) q2 += __shfl_xor_sync(~0u, q2, o);
        float rs = rsqrtf(q2 * (1.f / 128.f) + 1e-5f);
        float4 o4;
        o4.x = dx * rs * gm.x + bt.x;
        o4.y = dy * rs * gm.y + bt.y;
        o4.z = dz * rs * gm.z + bt.z;
        o4.w = dw * rs * gm.w + bt.w;
        *reinterpret_cast<float4*>(
            out + (size_t)(m0 + r) * TD + t * D + lane * 4) = o4;
    }
}

// ============================================================
extern "C" void kernel_launch(void* const* d_in, const int* in_sizes, int n_in,
                              void* d_out, int out_size)
{
    const float* X     = (const float*)d_in[0];
    const float* W1    = (const float*)d_in[1];
    const float* b1    = (const float*)d_in[2];
    const float* W2    = (const float*)d_in[3];
    const float* b2    = (const float*)d_in[4];
    const float* gamma = (const float*)d_in[5];
    const float* beta  = (const float*)d_in[6];
    float* out = (float*)d_out;

    const int smem_g1   = 4 * 9216 * 2;                       // 73,728 B
    const int smem_attn = (8704 + 9216) * 2 + 64 * 76 * 4;    // 55,296 B
    const int smem_g2   = (8704 + 128 * 136) * 2;             // 52,224 B
    cudaFuncSetAttribute(gemm1_kernel,
        cudaFuncAttributeMaxDynamicSharedMemorySize, smem_g1);
    cudaFuncSetAttribute(attn_kernel,
        cudaFuncAttributeMaxDynamicSharedMemorySize, smem_attn);
    cudaFuncSetAttribute(gemm2_ln_kernel,
        cudaFuncAttributeMaxDynamicSharedMemorySize, smem_g2);

    prep_w_kernel<<<1024, 256>>>(W1, W2);
    gemm1_kernel<<<dim3(32, SPLITK), 256, smem_g1>>>(X);
    reduce_relu_kernel<<<256, 256>>>(b1);
    attn_kernel<<<BATCH, 256, smem_attn>>>(X);
    gemm2_ln_kernel<<<dim3(64, 64), 256, smem_g2>>>(b2, gamma, beta, out);
}

// round 6
// speedup vs baseline: 3.6509x; 1.0610x over previous
#include <cuda_runtime.h>
#include <cuda_fp16.h>
#include <cstdint>

#define BATCH 4096
#define T 64
#define D 128
#define TD 8192
#define SPLITK 8

// Scratch (__device__ globals per allocation-free rule)
__device__ __half g_w1h[(size_t)D * TD];             // W1 fp16, [n][k] (2MB)
__device__ __half g_w2h[(size_t)TD * D];             // W2 fp16, [n][k] (2MB)
__device__ __half g_hp[(size_t)SPLITK * BATCH * D];  // gemm1 partials fp16 (8MB)
__device__ __half g_ht[(size_t)BATCH * D];           // relu(h+b1) fp16 (1MB)
__device__ __half g_ypart[(size_t)BATCH * TD];       // X + X_dot fp16 (64MB)

// ---------------- helpers ----------------
__device__ __forceinline__ unsigned pack2(float lo, float hi) {
    unsigned r;
    asm("cvt.rn.f16x2.f32 %0, %1, %2;" : "=r"(r) : "f"(hi), "f"(lo));
    return r;
}
__device__ __forceinline__ uint4 pack8(float4 v0, float4 v1) {
    uint4 u;
    u.x = pack2(v0.x, v0.y); u.y = pack2(v0.z, v0.w);
    u.z = pack2(v1.x, v1.y); u.w = pack2(v1.z, v1.w);
    return u;
}
__device__ __forceinline__ void mma_f16(float* c,
    unsigned a0, unsigned a1, unsigned a2, unsigned a3, unsigned b0, unsigned b1)
{
    asm volatile(
        "mma.sync.aligned.m16n8k16.row.col.f32.f16.f16.f32 "
        "{%0,%1,%2,%3}, {%4,%5,%6,%7}, {%8,%9}, {%0,%1,%2,%3};\n"
        : "+f"(c[0]), "+f"(c[1]), "+f"(c[2]), "+f"(c[3])
        : "r"(a0), "r"(a1), "r"(a2), "r"(a3), "r"(b0), "r"(b1));
}
__device__ __forceinline__ void cp16(__half* smem_dst, const __half* gsrc) {
    unsigned sa = (unsigned)__cvta_generic_to_shared(smem_dst);
    asm volatile("cp.async.cg.shared.global [%0], [%1], 16;\n" :: "r"(sa), "l"(gsrc));
}
__device__ __forceinline__ void ldsm_x4(unsigned& r0, unsigned& r1,
                                        unsigned& r2, unsigned& r3, const __half* p)
{
    unsigned a = (unsigned)__cvta_generic_to_shared(p);
    asm volatile("ldmatrix.sync.aligned.m8n8.x4.shared.b16 {%0,%1,%2,%3}, [%4];"
        : "=r"(r0), "=r"(r1), "=r"(r2), "=r"(r3) : "r"(a));
}
__device__ __forceinline__ void ldsm_x4_t(unsigned& r0, unsigned& r1,
                                          unsigned& r2, unsigned& r3, const __half* p)
{
    unsigned a = (unsigned)__cvta_generic_to_shared(p);
    asm volatile("ldmatrix.sync.aligned.m8n8.x4.trans.shared.b16 {%0,%1,%2,%3}, [%4];"
        : "=r"(r0), "=r"(r1), "=r"(r2), "=r"(r3) : "r"(a));
}
// A-style ldsm lane offset: 16x16 tile at (R, C), row stride S (halves)
#define LDSM_A_OFF(R, C, S)  (((R) + l7 + lb8 * 8) * (S) + (C) + lc16 * 8)
// B-style (non-trans) lane offset: 16 n-rows at N0, k cols at C
#define LDSM_B_OFF(N0, C, S) (((N0) + lc16 * 8 + l7) * (S) + (C) + lb8 * 8)

// ============================================================
// Prep: W1 (1M) and W2 (1M) fp32 -> fp16, layouts already [n][k]
// ============================================================
__global__ void __launch_bounds__(256) prep_w_kernel(
    const float* __restrict__ W1, const float* __restrict__ W2)
{
    size_t o = (size_t)(blockIdx.x * 256 + threadIdx.x) * 8;
    const size_t NW = (size_t)D * TD;
    const float* src = (o < NW) ? (W1 + o) : (W2 + (o - NW));
    __half* dst = (o < NW) ? (g_w1h + o) : (g_w2h + (o - NW));
    float4 v0 = *reinterpret_cast<const float4*>(src);
    float4 v1 = *reinterpret_cast<const float4*>(src + 4);
    *reinterpret_cast<uint4*>(dst) = pack8(v0, v1);
}

// ============================================================
// Kernel 1: split-K GEMM  h_part = X(4096x8192) @ W1^T (fp16 mma + ldmatrix)
// grid (32, 8), 256 thr. M_TILE=128, N=128, K chunk=1024, K_TILE=64.
// ============================================================
__global__ void __launch_bounds__(256, 2) gemm1_kernel(const float* __restrict__ X)
{
    extern __shared__ __half smh[];
    __half* Asm = smh;                 // 2 stages x 9216 halves (128 x 72)
    __half* Bsm = smh + 2 * 9216;

    const int m0 = blockIdx.x * 128;
    const int k0 = blockIdx.y * 1024;
    const int tid = threadIdx.x;
    const int wid = tid >> 5, lane = tid & 31;
    const int l7 = lane & 7, lb8 = (lane >> 3) & 1, lc16 = lane >> 4;
    const int wm = wid & 3, wn = wid >> 2;     // warp tile 32m x 64n

    int r4[4], o4[4];
#pragma unroll
    for (int i = 0; i < 4; i++) { int q = tid + i * 256; r4[i] = q >> 3; o4[i] = q & 7; }

    float acc[2][8][4];
#pragma unroll
    for (int m = 0; m < 2; m++)
#pragma unroll
        for (int i = 0; i < 8; i++)
#pragma unroll
            for (int j = 0; j < 4; j++) acc[m][i][j] = 0.f;

    float4 av[4][2];

#define G1_LDA(KK)                                                               \
    {                                                                            \
        _Pragma("unroll")                                                        \
        for (int i = 0; i < 4; i++) {                                            \
            const float* p = X + (size_t)(m0 + r4[i]) * TD + (KK) + o4[i] * 8;   \
            av[i][0] = *reinterpret_cast<const float4*>(p);                      \
            av[i][1] = *reinterpret_cast<const float4*>(p + 4);                  \
        }                                                                        \
    }
#define G1_STA(S)                                                                \
    {                                                                            \
        _Pragma("unroll")                                                        \
        for (int i = 0; i < 4; i++)                                              \
            *reinterpret_cast<uint4*>(Asm + (S) * 9216 + r4[i] * 72 + o4[i] * 8) \
                = pack8(av[i][0], av[i][1]);                                     \
    }
#define G1_CPB(S, KK)                                                            \
    {                                                                            \
        _Pragma("unroll")                                                        \
        for (int i = 0; i < 4; i++)                                              \
            cp16(Bsm + (S) * 9216 + r4[i] * 72 + o4[i] * 8,                      \
                 g_w1h + (size_t)r4[i] * TD + (KK) + o4[i] * 8);                 \
        asm volatile("cp.async.commit_group;\n");                                \
    }

    int kk = k0;
    G1_LDA(kk);
    G1_CPB(0, kk);
    G1_STA(0);
    asm volatile("cp.async.wait_group 0;\n");
    __syncthreads();

    for (int kt = 0; kt < 16; kt++) {
        const int cur = kt & 1, nxt = cur ^ 1;
        if (kt < 15) {
            G1_CPB(nxt, kk + 64);
            G1_LDA(kk + 64);
        }
        const __half* A = Asm + cur * 9216;
        const __half* B = Bsm + cur * 9216;
#pragma unroll
        for (int ks = 0; ks < 4; ks++) {
            unsigned a[2][4];
#pragma unroll
            for (int ms = 0; ms < 2; ms++)
                ldsm_x4(a[ms][0], a[ms][1], a[ms][2], a[ms][3],
                        A + LDSM_A_OFF(wm * 32 + ms * 16, ks * 16, 72));
#pragma unroll
            for (int ntp = 0; ntp < 4; ntp++) {
                unsigned b00, b01, b10, b11;
                ldsm_x4(b00, b01, b10, b11,
                        B + LDSM_B_OFF(wn * 64 + ntp * 16, ks * 16, 72));
#pragma unroll
                for (int ms = 0; ms < 2; ms++) {
                    mma_f16(acc[ms][ntp * 2],     a[ms][0], a[ms][1], a[ms][2], a[ms][3], b00, b01);
                    mma_f16(acc[ms][ntp * 2 + 1], a[ms][0], a[ms][1], a[ms][2], a[ms][3], b10, b11);
                }
            }
        }
        if (kt < 15) {
            G1_STA(nxt);
            asm volatile("cp.async.wait_group 0;\n");
        }
        __syncthreads();
        kk += 64;
    }

    __half* outp = g_hp + (size_t)blockIdx.y * BATCH * D;
    const int g = lane >> 2, tg = lane & 3;
#pragma unroll
    for (int ms = 0; ms < 2; ms++)
#pragma unroll
        for (int nt = 0; nt < 8; nt++) {
            int row = m0 + wm * 32 + ms * 16 + g;
            int col = wn * 64 + nt * 8 + 2 * tg;
            *reinterpret_cast<unsigned*>(outp + (size_t)row * D + col) =
                pack2(acc[ms][nt][0], acc[ms][nt][1]);
            *reinterpret_cast<unsigned*>(outp + (size_t)(row + 8) * D + col) =
                pack2(acc[ms][nt][2], acc[ms][nt][3]);
        }
}

// ============================================================
// Kernel 1b: g_ht = fp16( relu( sum_p g_hp[p] + b1 ) )
// ============================================================
__global__ void __launch_bounds__(256) reduce_relu_kernel(const float* __restrict__ b1)
{
    const int o = blockIdx.x * 256 + threadIdx.x;   // 65536 octets
    const size_t base = (size_t)o * 8;
    const int col = (o & 15) * 8;
    float4 s0 = *reinterpret_cast<const float4*>(b1 + col);
    float4 s1 = *reinterpret_cast<const float4*>(b1 + col + 4);
#pragma unroll
    for (int p = 0; p < SPLITK; p++) {
        uint4 u = *reinterpret_cast<const uint4*>(g_hp + (size_t)p * BATCH * D + base);
        float2 f0 = __half22float2(*reinterpret_cast<__half2*>(&u.x));
        float2 f1 = __half22float2(*reinterpret_cast<__half2*>(&u.y));
        float2 f2 = __half22float2(*reinterpret_cast<__half2*>(&u.z));
        float2 f3 = __half22float2(*reinterpret_cast<__half2*>(&u.w));
        s0.x += f0.x; s0.y += f0.y; s0.z += f1.x; s0.w += f1.y;
        s1.x += f2.x; s1.y += f2.y; s1.z += f3.x; s1.w += f3.y;
    }
    s0.x = fmaxf(s0.x, 0.f); s0.y = fmaxf(s0.y, 0.f);
    s0.z = fmaxf(s0.z, 0.f); s0.w = fmaxf(s0.w, 0.f);
    s1.x = fmaxf(s1.x, 0.f); s1.y = fmaxf(s1.y, 0.f);
    s1.z = fmaxf(s1.z, 0.f); s1.w = fmaxf(s1.w, 0.f);
    *reinterpret_cast<uint4*>(g_ht + base) = pack8(s0, s1);
}

// ============================================================
// Kernel 2: per-batch attention (fp16 mma + ldmatrix; no transpose buffer)
// smem: Xn[64][136]h, Ssf[64][76]f (Ps aliases, stride 152 h)
// ============================================================
__global__ void __launch_bounds__(256, 3) attn_kernel(const float* __restrict__ X)
{
    extern __shared__ __half smh[];
    __half* Xn  = smh;                                      // 64 x 136
    float*  Ssf = reinterpret_cast<float*>(smh + 8704);     // 64 x 76 fp32
    __half* Ps  = reinterpret_cast<__half*>(Ssf);           // stride 152 halves

    const int b = blockIdx.x;
    const float* Xb = X + (size_t)b * TD;
    const int tid = threadIdx.x, wid = tid >> 5, lane = tid & 31;
    const int g = lane >> 2, tg = lane & 3;
    const int l7 = lane & 7, lb8 = (lane >> 3) & 1, lc16 = lane >> 4;
    const int wm = wid & 3, wn = wid >> 2;

    // fill Xn (convert fp32 -> fp16)
#pragma unroll
    for (int i = 0; i < 4; i++) {
        int q = tid + i * 256;
        int r = q >> 4, o = q & 15;
        const float* p = Xb + r * D + o * 8;
        float4 v0 = *reinterpret_cast<const float4*>(p);
        float4 v1 = *reinterpret_cast<const float4*>(p + 4);
        *reinterpret_cast<uint4*>(Xn + r * 136 + o * 8) = pack8(v0, v1);
    }
    __syncthreads();

    // QK: scores = X X^T * scale; warp tile 16m x 32n
    {
        float acc[4][4];
#pragma unroll
        for (int i = 0; i < 4; i++)
#pragma unroll
            for (int j = 0; j < 4; j++) acc[i][j] = 0.f;
#pragma unroll
        for (int ks = 0; ks < 8; ks++) {
            unsigned a0, a1, a2, a3;
            ldsm_x4(a0, a1, a2, a3, Xn + LDSM_A_OFF(wm * 16, ks * 16, 136));
#pragma unroll
            for (int ntp = 0; ntp < 2; ntp++) {
                unsigned b00, b01, b10, b11;
                ldsm_x4(b00, b01, b10, b11,
                        Xn + LDSM_B_OFF(wn * 32 + ntp * 16, ks * 16, 136));
                mma_f16(acc[ntp * 2],     a0, a1, a2, a3, b00, b01);
                mma_f16(acc[ntp * 2 + 1], a0, a1, a2, a3, b10, b11);
            }
        }
        const float scale = 0.0883883476483184f;   // 128^-0.5
#pragma unroll
        for (int nt = 0; nt < 4; nt++) {
            int col = wn * 32 + nt * 8 + 2 * tg, row = wm * 16 + g;
            *reinterpret_cast<float2*>(Ssf + row * 76 + col) =
                make_float2(acc[nt][0] * scale, acc[nt][1] * scale);
            *reinterpret_cast<float2*>(Ssf + (row + 8) * 76 + col) =
                make_float2(acc[nt][2] * scale, acc[nt][3] * scale);
        }
    }
    __syncthreads();

    // softmax per row; write fp16 probs in place (Ps aliases Ss rows)
    for (int rr = 0; rr < 8; rr++) {
        int r = wid * 8 + rr;
        float v0 = Ssf[r * 76 + lane * 2], v1 = Ssf[r * 76 + lane * 2 + 1];
        float m = fmaxf(v0, v1);
#pragma unroll
        for (int o = 16; o > 0; o >>= 1) m = fmaxf(m, __shfl_xor_sync(~0u, m, o));
        float e0 = __expf(v0 - m), e1 = __expf(v1 - m);
        float s = e0 + e1;
#pragma unroll
        for (int o = 16; o > 0; o >>= 1) s += __shfl_xor_sync(~0u, s, o);
        float inv = 1.f / s;
        *reinterpret_cast<unsigned*>(Ps + r * 152 + lane * 2) = pack2(e0 * inv, e1 * inv);
    }
    __syncthreads();

    // PV: X_dot = attn @ X; warp tile 16m x 64n, K=64 tokens.
    // B fragments straight from Xn via ldmatrix.trans (hardware transpose).
    float acc[8][4];
#pragma unroll
    for (int i = 0; i < 8; i++)
#pragma unroll
        for (int j = 0; j < 4; j++) acc[i][j] = 0.f;
#pragma unroll
    for (int ks = 0; ks < 4; ks++) {
        unsigned a0, a1, a2, a3;
        ldsm_x4(a0, a1, a2, a3, Ps + LDSM_A_OFF(wm * 16, ks * 16, 152));
#pragma unroll
        for (int ntp = 0; ntp < 4; ntp++) {
            unsigned b00, b01, b10, b11;
            // trans tile: k-rows = s (ks*16..), n-cols = d (wn*64+ntp*16..)
            ldsm_x4_t(b00, b01, b10, b11,
                      Xn + LDSM_A_OFF(ks * 16, wn * 64 + ntp * 16, 136));
            mma_f16(acc[ntp * 2],     a0, a1, a2, a3, b00, b01);
            mma_f16(acc[ntp * 2 + 1], a0, a1, a2, a3, b10, b11);
        }
    }
    // epilogue: + X (from smem fp16), write ypart fp16
    __half* yp = g_ypart + (size_t)b * TD;
#pragma unroll
    for (int nt = 0; nt < 8; nt++) {
        int col = wn * 64 + nt * 8 + 2 * tg;
        int row = wm * 16 + g;
        float2 x0 = __half22float2(*reinterpret_cast<const __half2*>(Xn + row * 136 + col));
        float2 x1 = __half22float2(*reinterpret_cast<const __half2*>(Xn + (row + 8) * 136 + col));
        *reinterpret_cast<unsigned*>(yp + row * D + col) =
            pack2(acc[nt][0] + x0.x, acc[nt][1] + x0.y);
        *reinterpret_cast<unsigned*>(yp + (row + 8) * D + col) =
            pack2(acc[nt][2] + x1.x, acc[nt][3] + x1.y);
    }
}

// ============================================================
// Kernel 3: out = LN( ypart + b2 + g_ht @ W2^T ) * gamma + beta (fp16 mma + ldmatrix)
// grid (64, 64), 256 thr. M_TILE=64, N=128, K=128 single shot.
// ============================================================
__global__ void __launch_bounds__(256, 3) gemm2_ln_kernel(
    const float* __restrict__ b2, const float* __restrict__ gamma,
    const float* __restrict__ beta, float* __restrict__ out)
{
    extern __shared__ __half smh[];
    __half* As = smh;                   // 64 x 136
    __half* Bs = smh + 8704;            // 128 x 136
    float*  ys = reinterpret_cast<float*>(Bs);   // 64 x 132 fp32 (after mma)

    const int m0 = blockIdx.x * 64;
    const int t  = blockIdx.y;
    const int tid = threadIdx.x, wid = tid >> 5, lane = tid & 31;
    const int g = lane >> 2, tg = lane & 3;
    const int l7 = lane & 7, lb8 = (lane >> 3) & 1, lc16 = lane >> 4;
    const int wm = wid & 3, wn = wid >> 2;      // warp tile 16m x 64n

    // A fill: 64 rows x 128 halves
#pragma unroll
    for (int i = 0; i < 4; i++) {
        int q = tid + i * 256;
        int r = q >> 4, o = q & 15;
        *reinterpret_cast<uint4*>(As + r * 136 + o * 8) =
            *reinterpret_cast<const uint4*>(g_ht + (size_t)(m0 + r) * D + o * 8);
    }
    // B fill: cp.async of fp16 W2 rows (128 x 128)
#pragma unroll
    for (int i = 0; i < 8; i++) {
        int q = tid + i * 256;
        int n = q >> 4, o = q & 15;
        cp16(Bs + n * 136 + o * 8,
             g_w2h + (size_t)(t * D + n) * D + o * 8);
    }
    asm volatile("cp.async.commit_group;\n");
    asm volatile("cp.async.wait_group 0;\n");
    __syncthreads();

    float acc[8][4];
#pragma unroll
    for (int i = 0; i < 8; i++)
#pragma unroll
        for (int j = 0; j < 4; j++) acc[i][j] = 0.f;
#pragma unroll
    for (int ks = 0; ks < 8; ks++) {
        unsigned a0, a1, a2, a3;
        ldsm_x4(a0, a1, a2, a3, As + LDSM_A_OFF(wm * 16, ks * 16, 136));
#pragma unroll
        for (int ntp = 0; ntp < 4; ntp++) {
            unsigned b00, b01, b10, b11;
            ldsm_x4(b00, b01, b10, b11,
                    Bs + LDSM_B_OFF(wn * 64 + ntp * 16, ks * 16, 136));
            mma_f16(acc[ntp * 2],     a0, a1, a2, a3, b00, b01);
            mma_f16(acc[ntp * 2 + 1], a0, a1, a2, a3, b10, b11);
        }
    }
    __syncthreads();     // mma reads done; Bs region becomes ys

    // ys = ypart + b2
#pragma unroll
    for (int i = 0; i < 4; i++) {
        int q = tid + i * 256;
        int r = q >> 4, o = q & 15;
        uint4 u = *reinterpret_cast<const uint4*>(
            g_ypart + (size_t)(m0 + r) * TD + t * D + o * 8);
        float4 bb0 = *reinterpret_cast<const float4*>(b2 + t * D + o * 8);
        float4 bb1 = *reinterpret_cast<const float4*>(b2 + t * D + o * 8 + 4);
        float2 f0 = __half22float2(*reinterpret_cast<__half2*>(&u.x));
        float2 f1 = __half22float2(*reinterpret_cast<__half2*>(&u.y));
        float2 f2 = __half22float2(*reinterpret_cast<__half2*>(&u.z));
        float2 f3 = __half22float2(*reinterpret_cast<__half2*>(&u.w));
        float4 w0 = make_float4(f0.x + bb0.x, f0.y + bb0.y, f1.x + bb0.z, f1.y + bb0.w);
        float4 w1 = make_float4(f2.x + bb1.x, f2.y + bb1.y, f3.x + bb1.z, f3.y + bb1.w);
        *reinterpret_cast<float4*>(ys + r * 132 + o * 8)     = w0;
        *reinterpret_cast<float4*>(ys + r * 132 + o * 8 + 4) = w1;
    }
    __syncthreads();
#pragma unroll
    for (int nt = 0; nt < 8; nt++) {
        int col = wn * 64 + nt * 8 + 2 * tg, row = wm * 16 + g;
        ys[row * 132 + col]           += acc[nt][0];
        ys[row * 132 + col + 1]       += acc[nt][1];
        ys[(row + 8) * 132 + col]     += acc[nt][2];
        ys[(row + 8) * 132 + col + 1] += acc[nt][3];
    }
    __syncthreads();

    // LayerNorm; warp owns 8 rows
    float4 gm = *reinterpret_cast<const float4*>(gamma + lane * 4);
    float4 bt = *reinterpret_cast<const float4*>(beta + lane * 4);
    for (int rr = 0; rr < 8; rr++) {
        int r = wid * 8 + rr;
        float4 v = *reinterpret_cast<float4*>(ys + r * 132 + lane * 4);
        float s = v.x + v.y + v.z + v.w;
#pragma unroll
        for (int o = 16; o > 0; o >>= 1) s += __shfl_xor_sync(~0u, s, o);
        float mu = s * (1.f / 128.f);
        float dx = v.x - mu, dy = v.y - mu, dz = v.z - mu, dw = v.w - mu;
        float q2 = dx * dx + dy * dy + dz * dz + dw * dw;
#pragma unroll
        for (int o = 16; o > 0; o >>= 1) q2 += __shfl_xor_sync(~0u, q2, o);
        float rs = rsqrtf(q2 * (1.f / 128.f) + 1e-5f);
        float4 o4;
        o4.x = dx * rs * gm.x + bt.x;
        o4.y = dy * rs * gm.y + bt.y;
        o4.z = dz * rs * gm.z + bt.z;
        o4.w = dw * rs * gm.w + bt.w;
        *reinterpret_cast<float4*>(
            out + (size_t)(m0 + r) * TD + t * D + lane * 4) = o4;
    }
}

// ============================================================
extern "C" void kernel_launch(void* const* d_in, const int* in_sizes, int n_in,
                              void* d_out, int out_size)
{
    const float* X     = (const float*)d_in[0];
    const float* W1    = (const float*)d_in[1];
    const float* b1    = (const float*)d_in[2];
    const float* W2    = (const float*)d_in[3];
    const float* b2    = (const float*)d_in[4];
    const float* gamma = (const float*)d_in[5];
    const float* beta  = (const float*)d_in[6];
    float* out = (float*)d_out;

    const int smem_g1   = 4 * 9216 * 2;                 // 73,728 B
    const int smem_attn = 8704 * 2 + 64 * 76 * 4;       // 36,864 B
    const int smem_g2   = (8704 + 128 * 136) * 2;       // 52,224 B
    cudaFuncSetAttribute(gemm1_kernel,
        cudaFuncAttributeMaxDynamicSharedMemorySize, smem_g1);
    cudaFuncSetAttribute(attn_kernel,
        cudaFuncAttributeMaxDynamicSharedMemorySize, smem_attn);
    cudaFuncSetAttribute(gemm2_ln_kernel,
        cudaFuncAttributeMaxDynamicSharedMemorySize, smem_g2);

    prep_w_kernel<<<1024, 256>>>(W1, W2);
    gemm1_kernel<<<dim3(32, SPLITK), 256, smem_g1>>>(X);
    reduce_relu_kernel<<<256, 256>>>(b1);
    attn_kernel<<<BATCH, 256, smem_attn>>>(X);
    gemm2_ln_kernel<<<dim3(64, 64), 256, smem_g2>>>(b2, gamma, beta, out);
}

// round 7
// speedup vs baseline: 4.0312x; 1.1041x over previous
#include <cuda_runtime.h>
#include <cuda_fp16.h>
#include <cstdint>

#define BATCH 4096
#define T 64
#define D 128
#define TD 8192
#define SPLITK 8

// Scratch (__device__ globals per allocation-free rule)
__device__ __half g_w1h[(size_t)D * TD];             // W1 fp16, [n][k] (2MB)
__device__ __half g_w2h[(size_t)TD * D];             // W2 fp16, [n][k] (2MB)
__device__ __half g_hp[(size_t)SPLITK * BATCH * D];  // gemm1 partials fp16 (8MB)
__device__ __half g_ht[(size_t)BATCH * D];           // relu(h+b1) fp16 (1MB)
__device__ __half g_ypart[(size_t)BATCH * TD];       // X + X_dot fp16 (64MB)

// ---------------- helpers ----------------
__device__ __forceinline__ unsigned pack2(float lo, float hi) {
    unsigned r;
    asm("cvt.rn.f16x2.f32 %0, %1, %2;" : "=r"(r) : "f"(hi), "f"(lo));
    return r;
}
__device__ __forceinline__ uint4 pack8(float4 v0, float4 v1) {
    uint4 u;
    u.x = pack2(v0.x, v0.y); u.y = pack2(v0.z, v0.w);
    u.z = pack2(v1.x, v1.y); u.w = pack2(v1.z, v1.w);
    return u;
}
__device__ __forceinline__ void mma_f16(float* c,
    unsigned a0, unsigned a1, unsigned a2, unsigned a3, unsigned b0, unsigned b1)
{
    asm volatile(
        "mma.sync.aligned.m16n8k16.row.col.f32.f16.f16.f32 "
        "{%0,%1,%2,%3}, {%4,%5,%6,%7}, {%8,%9}, {%0,%1,%2,%3};\n"
        : "+f"(c[0]), "+f"(c[1]), "+f"(c[2]), "+f"(c[3])
        : "r"(a0), "r"(a1), "r"(a2), "r"(a3), "r"(b0), "r"(b1));
}
__device__ __forceinline__ void cp16(__half* smem_dst, const __half* gsrc) {
    unsigned sa = (unsigned)__cvta_generic_to_shared(smem_dst);
    asm volatile("cp.async.cg.shared.global [%0], [%1], 16;\n" :: "r"(sa), "l"(gsrc));
}
__device__ __forceinline__ void ldsm_x4(unsigned& r0, unsigned& r1,
                                        unsigned& r2, unsigned& r3, const __half* p)
{
    unsigned a = (unsigned)__cvta_generic_to_shared(p);
    asm volatile("ldmatrix.sync.aligned.m8n8.x4.shared.b16 {%0,%1,%2,%3}, [%4];"
        : "=r"(r0), "=r"(r1), "=r"(r2), "=r"(r3) : "r"(a));
}
__device__ __forceinline__ void ldsm_x4_t(unsigned& r0, unsigned& r1,
                                          unsigned& r2, unsigned& r3, const __half* p)
{
    unsigned a = (unsigned)__cvta_generic_to_shared(p);
    asm volatile("ldmatrix.sync.aligned.m8n8.x4.trans.shared.b16 {%0,%1,%2,%3}, [%4];"
        : "=r"(r0), "=r"(r1), "=r"(r2), "=r"(r3) : "r"(a));
}
// A-style ldsm lane offset: 16x16 tile at (R, C), row stride S (halves)
#define LDSM_A_OFF(R, C, S)  (((R) + l7 + lb8 * 8) * (S) + (C) + lc16 * 8)
// B-style (non-trans) lane offset: 16 n-rows at N0, k cols at C
#define LDSM_B_OFF(N0, C, S) (((N0) + lc16 * 8 + l7) * (S) + (C) + lb8 * 8)

// ============================================================
// Prep: W1 (1M) and W2 (1M) fp32 -> fp16, layouts already [n][k]
// ============================================================
__global__ void __launch_bounds__(256) prep_w_kernel(
    const float* __restrict__ W1, const float* __restrict__ W2)
{
    size_t o = (size_t)(blockIdx.x * 256 + threadIdx.x) * 8;
    const size_t NW = (size_t)D * TD;
    const float* src = (o < NW) ? (W1 + o) : (W2 + (o - NW));
    __half* dst = (o < NW) ? (g_w1h + o) : (g_w2h + (o - NW));
    float4 v0 = *reinterpret_cast<const float4*>(src);
    float4 v1 = *reinterpret_cast<const float4*>(src + 4);
    *reinterpret_cast<uint4*>(dst) = pack8(v0, v1);
}

// ============================================================
// Kernel 1: split-K GEMM  h_part = X(4096x8192) @ W1^T (fp16 mma + ldmatrix)
// grid (32, 8), 256 thr. M_TILE=128, N=128, K chunk=1024, K_TILE=64.
// Output staged through smem for coalesced uint4 stores.
// ============================================================
__global__ void __launch_bounds__(256, 2) gemm1_kernel(const float* __restrict__ X)
{
    extern __shared__ __half smh[];
    __half* Asm = smh;                 // 2 stages x 9216 halves (128 x 72)
    __half* Bsm = smh + 2 * 9216;

    const int m0 = blockIdx.x * 128;
    const int k0 = blockIdx.y * 1024;
    const int tid = threadIdx.x;
    const int wid = tid >> 5, lane = tid & 31;
    const int l7 = lane & 7, lb8 = (lane >> 3) & 1, lc16 = lane >> 4;
    const int g = lane >> 2, tg = lane & 3;
    const int wm = wid & 3, wn = wid >> 2;     // warp tile 32m x 64n

    int r4[4], o4[4];
#pragma unroll
    for (int i = 0; i < 4; i++) { int q = tid + i * 256; r4[i] = q >> 3; o4[i] = q & 7; }

    float acc[2][8][4];
#pragma unroll
    for (int m = 0; m < 2; m++)
#pragma unroll
        for (int i = 0; i < 8; i++)
#pragma unroll
            for (int j = 0; j < 4; j++) acc[m][i][j] = 0.f;

    float4 av[4][2];

#define G1_LDA(KK)                                                               \
    {                                                                            \
        _Pragma("unroll")                                                        \
        for (int i = 0; i < 4; i++) {                                            \
            const float* p = X + (size_t)(m0 + r4[i]) * TD + (KK) + o4[i] * 8;   \
            av[i][0] = *reinterpret_cast<const float4*>(p);                      \
            av[i][1] = *reinterpret_cast<const float4*>(p + 4);                  \
        }                                                                        \
    }
#define G1_STA(S)                                                                \
    {                                                                            \
        _Pragma("unroll")                                                        \
        for (int i = 0; i < 4; i++)                                              \
            *reinterpret_cast<uint4*>(Asm + (S) * 9216 + r4[i] * 72 + o4[i] * 8) \
                = pack8(av[i][0], av[i][1]);                                     \
    }
#define G1_CPB(S, KK)                                                            \
    {                                                                            \
        _Pragma("unroll")                                                        \
        for (int i = 0; i < 4; i++)                                              \
            cp16(Bsm + (S) * 9216 + r4[i] * 72 + o4[i] * 8,                      \
                 g_w1h + (size_t)r4[i] * TD + (KK) + o4[i] * 8);                 \
        asm volatile("cp.async.commit_group;\n");                                \
    }

    int kk = k0;
    G1_LDA(kk);
    G1_CPB(0, kk);
    G1_STA(0);
    asm volatile("cp.async.wait_group 0;\n");
    __syncthreads();

    for (int kt = 0; kt < 16; kt++) {
        const int cur = kt & 1, nxt = cur ^ 1;
        if (kt < 15) {
            G1_CPB(nxt, kk + 64);
            G1_LDA(kk + 64);
        }
        const __half* A = Asm + cur * 9216;
        const __half* B = Bsm + cur * 9216;
#pragma unroll
        for (int ks = 0; ks < 4; ks++) {
            unsigned a[2][4];
#pragma unroll
            for (int ms = 0; ms < 2; ms++)
                ldsm_x4(a[ms][0], a[ms][1], a[ms][2], a[ms][3],
                        A + LDSM_A_OFF(wm * 32 + ms * 16, ks * 16, 72));
#pragma unroll
            for (int ntp = 0; ntp < 4; ntp++) {
                unsigned b00, b01, b10, b11;
                ldsm_x4(b00, b01, b10, b11,
                        B + LDSM_B_OFF(wn * 64 + ntp * 16, ks * 16, 72));
#pragma unroll
                for (int ms = 0; ms < 2; ms++) {
                    mma_f16(acc[ms][ntp * 2],     a[ms][0], a[ms][1], a[ms][2], a[ms][3], b00, b01);
                    mma_f16(acc[ms][ntp * 2 + 1], a[ms][0], a[ms][1], a[ms][2], a[ms][3], b10, b11);
                }
            }
        }
        if (kt < 15) {
            G1_STA(nxt);
            asm volatile("cp.async.wait_group 0;\n");
        }
        __syncthreads();
        kk += 64;
    }

    // stage output in smem (stride 136), then coalesced uint4 stores
    __half* Sg = smh;   // 128 x 136 halves
#pragma unroll
    for (int ms = 0; ms < 2; ms++)
#pragma unroll
        for (int nt = 0; nt < 8; nt++) {
            int row = wm * 32 + ms * 16 + g;
            int col = wn * 64 + nt * 8 + 2 * tg;
            *reinterpret_cast<unsigned*>(Sg + row * 136 + col) =
                pack2(acc[ms][nt][0], acc[ms][nt][1]);
            *reinterpret_cast<unsigned*>(Sg + (row + 8) * 136 + col) =
                pack2(acc[ms][nt][2], acc[ms][nt][3]);
        }
    __syncthreads();
    __half* outp = g_hp + (size_t)blockIdx.y * BATCH * D;
#pragma unroll
    for (int i = 0; i < 8; i++) {
        int q = tid + i * 256;
        int r = q >> 4, o = q & 15;
        *reinterpret_cast<uint4*>(outp + (size_t)(m0 + r) * D + o * 8) =
            *reinterpret_cast<uint4*>(Sg + r * 136 + o * 8);
    }
}

// ============================================================
// Kernel 1b: g_ht = fp16( relu( sum_p g_hp[p] + b1 ) )
// grid 512 x 256, one uint2 (4 halves) per thread — fills the chip
// ============================================================
__global__ void __launch_bounds__(256) reduce_relu_kernel(const float* __restrict__ b1)
{
    const int idx = blockIdx.x * 256 + threadIdx.x;   // 131072 chunks
    const size_t base = (size_t)idx * 4;
    const int col = (idx & 31) * 4;
    float4 s = *reinterpret_cast<const float4*>(b1 + col);
#pragma unroll
    for (int p = 0; p < SPLITK; p++) {
        uint2 u = *reinterpret_cast<const uint2*>(g_hp + (size_t)p * BATCH * D + base);
        float2 f0 = __half22float2(*reinterpret_cast<__half2*>(&u.x));
        float2 f1 = __half22float2(*reinterpret_cast<__half2*>(&u.y));
        s.x += f0.x; s.y += f0.y; s.z += f1.x; s.w += f1.y;
    }
    s.x = fmaxf(s.x, 0.f); s.y = fmaxf(s.y, 0.f);
    s.z = fmaxf(s.z, 0.f); s.w = fmaxf(s.w, 0.f);
    uint2 o;
    o.x = pack2(s.x, s.y);
    o.y = pack2(s.z, s.w);
    *reinterpret_cast<uint2*>(g_ht + base) = o;
}

// ============================================================
// Kernel 2: per-batch attention (fp16 mma + ldmatrix)
// Output staged through smem; coalesced ypart stores; regs capped for 4 CTA/SM.
// smem: Xn[64][136]h, Ssf[64][76]f (Ps stride 152h / stage Sg stride 136h alias)
// ============================================================
__global__ void __launch_bounds__(256, 4) attn_kernel(const float* __restrict__ X)
{
    extern __shared__ __half smh[];
    __half* Xn  = smh;                                      // 64 x 136
    float*  Ssf = reinterpret_cast<float*>(smh + 8704);     // 64 x 76 fp32
    __half* Ps  = reinterpret_cast<__half*>(Ssf);           // stride 152 halves
    __half* Sg  = reinterpret_cast<__half*>(Ssf);           // stage, stride 136 halves

    const int b = blockIdx.x;
    const float* Xb = X + (size_t)b * TD;
    const int tid = threadIdx.x, wid = tid >> 5, lane = tid & 31;
    const int g = lane >> 2, tg = lane & 3;
    const int l7 = lane & 7, lb8 = (lane >> 3) & 1, lc16 = lane >> 4;
    const int wm = wid & 3, wn = wid >> 2;

    // fill Xn (convert fp32 -> fp16)
#pragma unroll
    for (int i = 0; i < 4; i++) {
        int q = tid + i * 256;
        int r = q >> 4, o = q & 15;
        const float* p = Xb + r * D + o * 8;
        float4 v0 = *reinterpret_cast<const float4*>(p);
        float4 v1 = *reinterpret_cast<const float4*>(p + 4);
        *reinterpret_cast<uint4*>(Xn + r * 136 + o * 8) = pack8(v0, v1);
    }
    __syncthreads();

    // QK: scores = X X^T * scale; warp tile 16m x 32n
    {
        float acc[4][4];
#pragma unroll
        for (int i = 0; i < 4; i++)
#pragma unroll
            for (int j = 0; j < 4; j++) acc[i][j] = 0.f;
#pragma unroll
        for (int ks = 0; ks < 8; ks++) {
            unsigned a0, a1, a2, a3;
            ldsm_x4(a0, a1, a2, a3, Xn + LDSM_A_OFF(wm * 16, ks * 16, 136));
#pragma unroll
            for (int ntp = 0; ntp < 2; ntp++) {
                unsigned b00, b01, b10, b11;
                ldsm_x4(b00, b01, b10, b11,
                        Xn + LDSM_B_OFF(wn * 32 + ntp * 16, ks * 16, 136));
                mma_f16(acc[ntp * 2],     a0, a1, a2, a3, b00, b01);
                mma_f16(acc[ntp * 2 + 1], a0, a1, a2, a3, b10, b11);
            }
        }
        const float scale = 0.0883883476483184f;   // 128^-0.5
#pragma unroll
        for (int nt = 0; nt < 4; nt++) {
            int col = wn * 32 + nt * 8 + 2 * tg, row = wm * 16 + g;
            *reinterpret_cast<float2*>(Ssf + row * 76 + col) =
                make_float2(acc[nt][0] * scale, acc[nt][1] * scale);
            *reinterpret_cast<float2*>(Ssf + (row + 8) * 76 + col) =
                make_float2(acc[nt][2] * scale, acc[nt][3] * scale);
        }
    }
    __syncthreads();

    // softmax per row; write fp16 probs in place (Ps aliases Ss rows)
    for (int rr = 0; rr < 8; rr++) {
        int r = wid * 8 + rr;
        float v0 = Ssf[r * 76 + lane * 2], v1 = Ssf[r * 76 + lane * 2 + 1];
        float m = fmaxf(v0, v1);
#pragma unroll
        for (int o = 16; o > 0; o >>= 1) m = fmaxf(m, __shfl_xor_sync(~0u, m, o));
        float e0 = __expf(v0 - m), e1 = __expf(v1 - m);
        float s = e0 + e1;
#pragma unroll
        for (int o = 16; o > 0; o >>= 1) s += __shfl_xor_sync(~0u, s, o);
        float inv = 1.f / s;
        *reinterpret_cast<unsigned*>(Ps + r * 152 + lane * 2) = pack2(e0 * inv, e1 * inv);
    }
    __syncthreads();

    // PV: X_dot = attn @ X; warp tile 16m x 64n, K=64 tokens.
    float acc[8][4];
#pragma unroll
    for (int i = 0; i < 8; i++)
#pragma unroll
        for (int j = 0; j < 4; j++) acc[i][j] = 0.f;
#pragma unroll
    for (int ks = 0; ks < 4; ks++) {
        unsigned a0, a1, a2, a3;
        ldsm_x4(a0, a1, a2, a3, Ps + LDSM_A_OFF(wm * 16, ks * 16, 152));
#pragma unroll
        for (int ntp = 0; ntp < 4; ntp++) {
            unsigned b00, b01, b10, b11;
            ldsm_x4_t(b00, b01, b10, b11,
                      Xn + LDSM_A_OFF(ks * 16, wn * 64 + ntp * 16, 136));
            mma_f16(acc[ntp * 2],     a0, a1, a2, a3, b00, b01);
            mma_f16(acc[ntp * 2 + 1], a0, a1, a2, a3, b10, b11);
        }
    }
    __syncthreads();   // all PV reads of Ps done — safe to overwrite as stage

    // stage PV result (fp16) into Sg (stride 136)
#pragma unroll
    for (int nt = 0; nt < 8; nt++) {
        int col = wn * 64 + nt * 8 + 2 * tg;
        int row = wm * 16 + g;
        *reinterpret_cast<unsigned*>(Sg + row * 136 + col) =
            pack2(acc[nt][0], acc[nt][1]);
        *reinterpret_cast<unsigned*>(Sg + (row + 8) * 136 + col) =
            pack2(acc[nt][2], acc[nt][3]);
    }
    __syncthreads();

    // coalesced ypart = stage + X (fp16 adds), uint4 stores
    __half* yp = g_ypart + (size_t)b * TD;
#pragma unroll
    for (int i = 0; i < 4; i++) {
        int q = tid + i * 256;
        int r = q >> 4, o = q & 15;
        uint4 s = *reinterpret_cast<uint4*>(Sg + r * 136 + o * 8);
        uint4 x = *reinterpret_cast<uint4*>(Xn + r * 136 + o * 8);
        uint4 w;
        reinterpret_cast<__half2*>(&w)[0] =
            __hadd2(reinterpret_cast<__half2*>(&s)[0], reinterpret_cast<__half2*>(&x)[0]);
        reinterpret_cast<__half2*>(&w)[1] =
            __hadd2(reinterpret_cast<__half2*>(&s)[1], reinterpret_cast<__half2*>(&x)[1]);
        reinterpret_cast<__half2*>(&w)[2] =
            __hadd2(reinterpret_cast<__half2*>(&s)[2], reinterpret_cast<__half2*>(&x)[2]);
        reinterpret_cast<__half2*>(&w)[3] =
            __hadd2(reinterpret_cast<__half2*>(&s)[3], reinterpret_cast<__half2*>(&x)[3]);
        *reinterpret_cast<uint4*>(yp + r * D + o * 8) = w;
    }
}

// ============================================================
// Kernel 3: out = LN( ypart + b2 + g_ht @ W2^T ) * gamma + beta
// grid (32, 64), 256 thr. M_TILE=128, N=128, K=128.
// ypart prefetched via cp.async (group overlapped with mainloop).
// smem: As[128][136] + Bs[128][136] + Yp[128][136]; ys fp32 [128][132] aliases As+Bs.
// ============================================================
__global__ void __launch_bounds__(256, 2) gemm2_ln_kernel(
    const float* __restrict__ b2, const float* __restrict__ gamma,
    const float* __restrict__ beta, float* __restrict__ out)
{
    extern __shared__ __half smh[];
    __half* As = smh;                     // 128 x 136
    __half* Bs = smh + 17408;             // 128 x 136
    __half* Yp = smh + 34816;             // 128 x 136
    float*  ys = reinterpret_cast<float*>(smh);   // 128 x 132 fp32 (after mma)

    const int m0 = blockIdx.x * 128;
    const int t  = blockIdx.y;
    const int tid = threadIdx.x, wid = tid >> 5, lane = tid & 31;
    const int g = lane >> 2, tg = lane & 3;
    const int l7 = lane & 7, lb8 = (lane >> 3) & 1, lc16 = lane >> 4;
    const int wm = wid & 3, wn = wid >> 2;      // warp tile 32m x 64n

    // group 0: A (relu(h)) + B (W2 token tile)
#pragma unroll
    for (int i = 0; i < 8; i++) {
        int q = tid + i * 256;
        int r = q >> 4, o = q & 15;
        cp16(As + r * 136 + o * 8, g_ht + (size_t)(m0 + r) * D + o * 8);
        cp16(Bs + r * 136 + o * 8, g_w2h + (size_t)(t * D + r) * D + o * 8);
    }
    asm volatile("cp.async.commit_group;\n");
    // group 1: ypart tile (consumed only in epilogue — overlaps mainloop)
#pragma unroll
    for (int i = 0; i < 8; i++) {
        int q = tid + i * 256;
        int r = q >> 4, o = q & 15;
        cp16(Yp + r * 136 + o * 8, g_ypart + (size_t)(m0 + r) * TD + t * D + o * 8);
    }
    asm volatile("cp.async.commit_group;\n");
    asm volatile("cp.async.wait_group 1;\n");   // A+B ready; Yp may be in flight
    __syncthreads();

    float acc[2][8][4];
#pragma unroll
    for (int m = 0; m < 2; m++)
#pragma unroll
        for (int i = 0; i < 8; i++)
#pragma unroll
            for (int j = 0; j < 4; j++) acc[m][i][j] = 0.f;

#pragma unroll
    for (int ks = 0; ks < 8; ks++) {
        unsigned a[2][4];
#pragma unroll
        for (int ms = 0; ms < 2; ms++)
            ldsm_x4(a[ms][0], a[ms][1], a[ms][2], a[ms][3],
                    As + LDSM_A_OFF(wm * 32 + ms * 16, ks * 16, 136));
#pragma unroll
        for (int ntp = 0; ntp < 4; ntp++) {
            unsigned b00, b01, b10, b11;
            ldsm_x4(b00, b01, b10, b11,
                    Bs + LDSM_B_OFF(wn * 64 + ntp * 16, ks * 16, 136));
#pragma unroll
            for (int ms = 0; ms < 2; ms++) {
                mma_f16(acc[ms][ntp * 2],     a[ms][0], a[ms][1], a[ms][2], a[ms][3], b00, b01);
                mma_f16(acc[ms][ntp * 2 + 1], a[ms][0], a[ms][1], a[ms][2], a[ms][3], b10, b11);
            }
        }
    }
    asm volatile("cp.async.wait_group 0;\n");   // Yp landed
    __syncthreads();                            // mma reads done; As+Bs become ys

    // ys = Yp + b2 (fp32)
#pragma unroll
    for (int i = 0; i < 8; i++) {
        int q = tid + i * 256;
        int r = q >> 4, o = q & 15;
        uint4 u = *reinterpret_cast<uint4*>(Yp + r * 136 + o * 8);
        float4 bb0 = *reinterpret_cast<const float4*>(b2 + t * D + o * 8);
        float4 bb1 = *reinterpret_cast<const float4*>(b2 + t * D + o * 8 + 4);
        float2 f0 = __half22float2(*reinterpret_cast<__half2*>(&u.x));
        float2 f1 = __half22float2(*reinterpret_cast<__half2*>(&u.y));
        float2 f2 = __half22float2(*reinterpret_cast<__half2*>(&u.z));
        float2 f3 = __half22float2(*reinterpret_cast<__half2*>(&u.w));
        *reinterpret_cast<float4*>(ys + r * 132 + o * 8) =
            make_float4(f0.x + bb0.x, f0.y + bb0.y, f1.x + bb0.z, f1.y + bb0.w);
        *reinterpret_cast<float4*>(ys + r * 132 + o * 8 + 4) =
            make_float4(f2.x + bb1.x, f2.y + bb1.y, f3.x + bb1.z, f3.y + bb1.w);
    }
    __syncthreads();
#pragma unroll
    for (int ms = 0; ms < 2; ms++)
#pragma unroll
        for (int nt = 0; nt < 8; nt++) {
            int row = wm * 32 + ms * 16 + g;
            int col = wn * 64 + nt * 8 + 2 * tg;
            ys[row * 132 + col]           += acc[ms][nt][0];
            ys[row * 132 + col + 1]       += acc[ms][nt][1];
            ys[(row + 8) * 132 + col]     += acc[ms][nt][2];
            ys[(row + 8) * 132 + col + 1] += acc[ms][nt][3];
        }
    __syncthreads();

    // LayerNorm; warp owns 16 rows
    float4 gm = *reinterpret_cast<const float4*>(gamma + lane * 4);
    float4 bt = *reinterpret_cast<const float4*>(beta + lane * 4);
    for (int rr = 0; rr < 16; rr++) {
        int r = wid * 16 + rr;
        float4 v = *reinterpret_cast<float4*>(ys + r * 132 + lane * 4);
        float s = v.x + v.y + v.z + v.w;
#pragma unroll
        for (int o = 16; o > 0; o >>= 1) s += __shfl_xor_sync(~0u, s, o);
        float mu = s * (1.f / 128.f);
        float dx = v.x - mu, dy = v.y - mu, dz = v.z - mu, dw = v.w - mu;
        float q2 = dx * dx + dy * dy + dz * dz + dw * dw;
#pragma unroll
        for (int o = 16; o > 0; o >>= 1) q2 += __shfl_xor_sync(~0u, q2, o);
        float rs = rsqrtf(q2 * (1.f / 128.f) + 1e-5f);
        float4 o4;
        o4.x = dx * rs * gm.x + bt.x;
        o4.y = dy * rs * gm.y + bt.y;
        o4.z = dz * rs * gm.z + bt.z;
        o4.w = dw * rs * gm.w + bt.w;
        *reinterpret_cast<float4*>(
            out + (size_t)(m0 + r) * TD + t * D + lane * 4) = o4;
    }
}

// ============================================================
extern "C" void kernel_launch(void* const* d_in, const int* in_sizes, int n_in,
                              void* d_out, int out_size)
{
    const float* X     = (const float*)d_in[0];
    const float* W1    = (const float*)d_in[1];
    const float* b1    = (const float*)d_in[2];
    const float* W2    = (const float*)d_in[3];
    const float* b2    = (const float*)d_in[4];
    const float* gamma = (const float*)d_in[5];
    const float* beta  = (const float*)d_in[6];
    float* out = (float*)d_out;

    const int smem_g1   = 4 * 9216 * 2;                 // 73,728 B
    const int smem_attn = 8704 * 2 + 64 * 76 * 4;       // 36,864 B
    const int smem_g2   = 3 * 17408 * 2;                // 104,448 B
    cudaFuncSetAttribute(gemm1_kernel,
        cudaFuncAttributeMaxDynamicSharedMemorySize, smem_g1);
    cudaFuncSetAttribute(attn_kernel,
        cudaFuncAttributeMaxDynamicSharedMemorySize, smem_attn);
    cudaFuncSetAttribute(gemm2_ln_kernel,
        cudaFuncAttributeMaxDynamicSharedMemorySize, smem_g2);

    prep_w_kernel<<<1024, 256>>>(W1, W2);
    gemm1_kernel<<<dim3(32, SPLITK), 256, smem_g1>>>(X);
    reduce_relu_kernel<<<512, 256>>>(b1);
    attn_kernel<<<BATCH, 256, smem_attn>>>(X);
    gemm2_ln_kernel<<<dim3(32, 64), 256, smem_g2>>>(b2, gamma, beta, out);
}

// round 8
// speedup vs baseline: 4.3038x; 1.0676x over previous
#include <cuda_runtime.h>
#include <cuda_fp16.h>
#include <cstdint>

#define BATCH 4096
#define T 64
#define D 128
#define TD 8192
#define SPLITK 8

// Scratch (__device__ globals per allocation-free rule)
__device__ __half g_w1h[(size_t)D * TD];             // W1 fp16, [n][k] (2MB)
__device__ __half g_w2h[(size_t)TD * D];             // W2 fp16, [n][k] (2MB)
__device__ __half g_hp[(size_t)SPLITK * BATCH * D];  // gemm1 partials fp16 (8MB)
__device__ __half g_ht[(size_t)BATCH * D];           // relu(h+b1) fp16 (1MB)
__device__ __half g_ypart[(size_t)BATCH * TD];       // X + X_dot fp16 (64MB)

// ---------------- helpers ----------------
__device__ __forceinline__ unsigned pack2(float lo, float hi) {
    unsigned r;
    asm("cvt.rn.f16x2.f32 %0, %1, %2;" : "=r"(r) : "f"(hi), "f"(lo));
    return r;
}
__device__ __forceinline__ uint4 pack8(float4 v0, float4 v1) {
    uint4 u;
    u.x = pack2(v0.x, v0.y); u.y = pack2(v0.z, v0.w);
    u.z = pack2(v1.x, v1.y); u.w = pack2(v1.z, v1.w);
    return u;
}
__device__ __forceinline__ void mma_f16(float* c,
    unsigned a0, unsigned a1, unsigned a2, unsigned a3, unsigned b0, unsigned b1)
{
    asm volatile(
        "mma.sync.aligned.m16n8k16.row.col.f32.f16.f16.f32 "
        "{%0,%1,%2,%3}, {%4,%5,%6,%7}, {%8,%9}, {%0,%1,%2,%3};\n"
        : "+f"(c[0]), "+f"(c[1]), "+f"(c[2]), "+f"(c[3])
        : "r"(a0), "r"(a1), "r"(a2), "r"(a3), "r"(b0), "r"(b1));
}
__device__ __forceinline__ void cp16(__half* smem_dst, const __half* gsrc) {
    unsigned sa = (unsigned)__cvta_generic_to_shared(smem_dst);
    asm volatile("cp.async.cg.shared.global [%0], [%1], 16;\n" :: "r"(sa), "l"(gsrc));
}
__device__ __forceinline__ void ldsm_x4(unsigned& r0, unsigned& r1,
                                        unsigned& r2, unsigned& r3, const __half* p)
{
    unsigned a = (unsigned)__cvta_generic_to_shared(p);
    asm volatile("ldmatrix.sync.aligned.m8n8.x4.shared.b16 {%0,%1,%2,%3}, [%4];"
        : "=r"(r0), "=r"(r1), "=r"(r2), "=r"(r3) : "r"(a));
}
__device__ __forceinline__ void ldsm_x4_t(unsigned& r0, unsigned& r1,
                                          unsigned& r2, unsigned& r3, const __half* p)
{
    unsigned a = (unsigned)__cvta_generic_to_shared(p);
    asm volatile("ldmatrix.sync.aligned.m8n8.x4.trans.shared.b16 {%0,%1,%2,%3}, [%4];"
        : "=r"(r0), "=r"(r1), "=r"(r2), "=r"(r3) : "r"(a));
}
// A-style ldsm lane offset: 16x16 tile at (R, C), row stride S (halves)
#define LDSM_A_OFF(R, C, S)  (((R) + l7 + lb8 * 8) * (S) + (C) + lc16 * 8)
// B-style (non-trans) lane offset: 16 n-rows at N0, k cols at C
#define LDSM_B_OFF(N0, C, S) (((N0) + lc16 * 8 + l7) * (S) + (C) + lb8 * 8)

// ============================================================
// Prep: W1 (1M) and W2 (1M) fp32 -> fp16, layouts already [n][k]
// ============================================================
__global__ void __launch_bounds__(256) prep_w_kernel(
    const float* __restrict__ W1, const float* __restrict__ W2)
{
    size_t o = (size_t)(blockIdx.x * 256 + threadIdx.x) * 8;
    const size_t NW = (size_t)D * TD;
    const float* src = (o < NW) ? (W1 + o) : (W2 + (o - NW));
    __half* dst = (o < NW) ? (g_w1h + o) : (g_w2h + (o - NW));
    float4 v0 = *reinterpret_cast<const float4*>(src);
    float4 v1 = *reinterpret_cast<const float4*>(src + 4);
    *reinterpret_cast<uint4*>(dst) = pack8(v0, v1);
}

// ============================================================
// Kernel 1: split-K GEMM  h_part = X(4096x8192) @ W1^T (fp16 mma + ldmatrix)
// grid (32, 8), 256 thr. M_TILE=128, N=128, K chunk=1024, K_TILE=64.
// ============================================================
__global__ void __launch_bounds__(256, 2) gemm1_kernel(const float* __restrict__ X)
{
    extern __shared__ __half smh[];
    __half* Asm = smh;                 // 2 stages x 9216 halves (128 x 72)
    __half* Bsm = smh + 2 * 9216;

    const int m0 = blockIdx.x * 128;
    const int k0 = blockIdx.y * 1024;
    const int tid = threadIdx.x;
    const int wid = tid >> 5, lane = tid & 31;
    const int l7 = lane & 7, lb8 = (lane >> 3) & 1, lc16 = lane >> 4;
    const int g = lane >> 2, tg = lane & 3;
    const int wm = wid & 3, wn = wid >> 2;     // warp tile 32m x 64n

    int r4[4], o4[4];
#pragma unroll
    for (int i = 0; i < 4; i++) { int q = tid + i * 256; r4[i] = q >> 3; o4[i] = q & 7; }

    float acc[2][8][4];
#pragma unroll
    for (int m = 0; m < 2; m++)
#pragma unroll
        for (int i = 0; i < 8; i++)
#pragma unroll
            for (int j = 0; j < 4; j++) acc[m][i][j] = 0.f;

    float4 av[4][2];

#define G1_LDA(KK)                                                               \
    {                                                                            \
        _Pragma("unroll")                                                        \
        for (int i = 0; i < 4; i++) {                                            \
            const float* p = X + (size_t)(m0 + r4[i]) * TD + (KK) + o4[i] * 8;   \
            av[i][0] = *reinterpret_cast<const float4*>(p);                      \
            av[i][1] = *reinterpret_cast<const float4*>(p + 4);                  \
        }                                                                        \
    }
#define G1_STA(S)                                                                \
    {                                                                            \
        _Pragma("unroll")                                                        \
        for (int i = 0; i < 4; i++)                                              \
            *reinterpret_cast<uint4*>(Asm + (S) * 9216 + r4[i] * 72 + o4[i] * 8) \
                = pack8(av[i][0], av[i][1]);                                     \
    }
#define G1_CPB(S, KK)                                                            \
    {                                                                            \
        _Pragma("unroll")                                                        \
        for (int i = 0; i < 4; i++)                                              \
            cp16(Bsm + (S) * 9216 + r4[i] * 72 + o4[i] * 8,                      \
                 g_w1h + (size_t)r4[i] * TD + (KK) + o4[i] * 8);                 \
        asm volatile("cp.async.commit_group;\n");                                \
    }

    int kk = k0;
    G1_LDA(kk);
    G1_CPB(0, kk);
    G1_STA(0);
    asm volatile("cp.async.wait_group 0;\n");
    __syncthreads();

    for (int kt = 0; kt < 16; kt++) {
        const int cur = kt & 1, nxt = cur ^ 1;
        if (kt < 15) {
            G1_CPB(nxt, kk + 64);
            G1_LDA(kk + 64);
        }
        const __half* A = Asm + cur * 9216;
        const __half* B = Bsm + cur * 9216;
#pragma unroll
        for (int ks = 0; ks < 4; ks++) {
            unsigned a[2][4];
#pragma unroll
            for (int ms = 0; ms < 2; ms++)
                ldsm_x4(a[ms][0], a[ms][1], a[ms][2], a[ms][3],
                        A + LDSM_A_OFF(wm * 32 + ms * 16, ks * 16, 72));
#pragma unroll
            for (int ntp = 0; ntp < 4; ntp++) {
                unsigned b00, b01, b10, b11;
                ldsm_x4(b00, b01, b10, b11,
                        B + LDSM_B_OFF(wn * 64 + ntp * 16, ks * 16, 72));
#pragma unroll
                for (int ms = 0; ms < 2; ms++) {
                    mma_f16(acc[ms][ntp * 2],     a[ms][0], a[ms][1], a[ms][2], a[ms][3], b00, b01);
                    mma_f16(acc[ms][ntp * 2 + 1], a[ms][0], a[ms][1], a[ms][2], a[ms][3], b10, b11);
                }
            }
        }
        if (kt < 15) {
            G1_STA(nxt);
            asm volatile("cp.async.wait_group 0;\n");
        }
        __syncthreads();
        kk += 64;
    }

    // stage output in smem (stride 136), then coalesced uint4 stores
    __half* Sg = smh;   // 128 x 136 halves
#pragma unroll
    for (int ms = 0; ms < 2; ms++)
#pragma unroll
        for (int nt = 0; nt < 8; nt++) {
            int row = wm * 32 + ms * 16 + g;
            int col = wn * 64 + nt * 8 + 2 * tg;
            *reinterpret_cast<unsigned*>(Sg + row * 136 + col) =
                pack2(acc[ms][nt][0], acc[ms][nt][1]);
            *reinterpret_cast<unsigned*>(Sg + (row + 8) * 136 + col) =
                pack2(acc[ms][nt][2], acc[ms][nt][3]);
        }
    __syncthreads();
    __half* outp = g_hp + (size_t)blockIdx.y * BATCH * D;
#pragma unroll
    for (int i = 0; i < 8; i++) {
        int q = tid + i * 256;
        int r = q >> 4, o = q & 15;
        *reinterpret_cast<uint4*>(outp + (size_t)(m0 + r) * D + o * 8) =
            *reinterpret_cast<uint4*>(Sg + r * 136 + o * 8);
    }
}

// ============================================================
// Kernel 1b: g_ht = fp16( relu( sum_p g_hp[p] + b1 ) )
// ============================================================
__global__ void __launch_bounds__(256) reduce_relu_kernel(const float* __restrict__ b1)
{
    const int idx = blockIdx.x * 256 + threadIdx.x;   // 131072 chunks
    const size_t base = (size_t)idx * 4;
    const int col = (idx & 31) * 4;
    float4 s = *reinterpret_cast<const float4*>(b1 + col);
#pragma unroll
    for (int p = 0; p < SPLITK; p++) {
        uint2 u = *reinterpret_cast<const uint2*>(g_hp + (size_t)p * BATCH * D + base);
        float2 f0 = __half22float2(*reinterpret_cast<__half2*>(&u.x));
        float2 f1 = __half22float2(*reinterpret_cast<__half2*>(&u.y));
        s.x += f0.x; s.y += f0.y; s.z += f1.x; s.w += f1.y;
    }
    s.x = fmaxf(s.x, 0.f); s.y = fmaxf(s.y, 0.f);
    s.z = fmaxf(s.z, 0.f); s.w = fmaxf(s.w, 0.f);
    uint2 o;
    o.x = pack2(s.x, s.y);
    o.y = pack2(s.z, s.w);
    *reinterpret_cast<uint2*>(g_ht + base) = o;
}

// ============================================================
// Kernel 2: per-batch attention (fp16 mma + ldmatrix + REGISTER softmax)
// smem: Xn[64][136]h, Ps[64][136]h (probs; later output stage), sst stats
// ============================================================
__global__ void __launch_bounds__(256, 4) attn_kernel(const float* __restrict__ X)
{
    extern __shared__ __half smh[];
    __half* Xn = smh;                  // 64 x 136
    __half* Ps = smh + 8704;           // 64 x 136 (fp16 probs; stage alias later)
    __shared__ float2 sst[4][2][16];   // (wm, wn, row-in-warp) partial (max, sum)

    const int b = blockIdx.x;
    const float* Xb = X + (size_t)b * TD;
    const int tid = threadIdx.x, wid = tid >> 5, lane = tid & 31;
    const int g = lane >> 2, tg = lane & 3;
    const int l7 = lane & 7, lb8 = (lane >> 3) & 1, lc16 = lane >> 4;
    const int wm = wid & 3, wn = wid >> 2;

    // fill Xn (convert fp32 -> fp16)
#pragma unroll
    for (int i = 0; i < 4; i++) {
        int q = tid + i * 256;
        int r = q >> 4, o = q & 15;
        const float* p = Xb + r * D + o * 8;
        float4 v0 = *reinterpret_cast<const float4*>(p);
        float4 v1 = *reinterpret_cast<const float4*>(p + 4);
        *reinterpret_cast<uint4*>(Xn + r * 136 + o * 8) = pack8(v0, v1);
    }
    __syncthreads();

    // QK: scores = X X^T * scale; warp tile 16m x 32n — kept in registers
    float sc[4][4];
#pragma unroll
    for (int i = 0; i < 4; i++)
#pragma unroll
        for (int j = 0; j < 4; j++) sc[i][j] = 0.f;
#pragma unroll
    for (int ks = 0; ks < 8; ks++) {
        unsigned a0, a1, a2, a3;
        ldsm_x4(a0, a1, a2, a3, Xn + LDSM_A_OFF(wm * 16, ks * 16, 136));
#pragma unroll
        for (int ntp = 0; ntp < 2; ntp++) {
            unsigned b00, b01, b10, b11;
            ldsm_x4(b00, b01, b10, b11,
                    Xn + LDSM_B_OFF(wn * 32 + ntp * 16, ks * 16, 136));
            mma_f16(sc[ntp * 2],     a0, a1, a2, a3, b00, b01);
            mma_f16(sc[ntp * 2 + 1], a0, a1, a2, a3, b10, b11);
        }
    }

    // ---- register softmax ----
    // thread holds rows (wm*16+g) [sc[nt][0..1]] and (+8) [sc[nt][2..3]],
    // cols wn*32 + nt*8 + 2tg(+1). Row is spread over the 4 lanes of a quad
    // (lane = 4g+tg) within this warp + the sibling warp (wn^1).
    const float scale = 0.0883883476483184f;   // 128^-0.5
    float m0 = -1e30f, m1 = -1e30f;
#pragma unroll
    for (int nt = 0; nt < 4; nt++) {
        sc[nt][0] *= scale; sc[nt][1] *= scale;
        sc[nt][2] *= scale; sc[nt][3] *= scale;
        m0 = fmaxf(m0, fmaxf(sc[nt][0], sc[nt][1]));
        m1 = fmaxf(m1, fmaxf(sc[nt][2], sc[nt][3]));
    }
    m0 = fmaxf(m0, __shfl_xor_sync(~0u, m0, 1));
    m0 = fmaxf(m0, __shfl_xor_sync(~0u, m0, 2));
    m1 = fmaxf(m1, __shfl_xor_sync(~0u, m1, 1));
    m1 = fmaxf(m1, __shfl_xor_sync(~0u, m1, 2));
    float s0 = 0.f, s1 = 0.f;
#pragma unroll
    for (int nt = 0; nt < 4; nt++) {
        sc[nt][0] = __expf(sc[nt][0] - m0); s0 += sc[nt][0];
        sc[nt][1] = __expf(sc[nt][1] - m0); s0 += sc[nt][1];
        sc[nt][2] = __expf(sc[nt][2] - m1); s1 += sc[nt][2];
        sc[nt][3] = __expf(sc[nt][3] - m1); s1 += sc[nt][3];
    }
    s0 += __shfl_xor_sync(~0u, s0, 1); s0 += __shfl_xor_sync(~0u, s0, 2);
    s1 += __shfl_xor_sync(~0u, s1, 1); s1 += __shfl_xor_sync(~0u, s1, 2);
    if (tg == 0) {
        sst[wm][wn][g]     = make_float2(m0, s0);
        sst[wm][wn][8 + g] = make_float2(m1, s1);
    }
    __syncthreads();
    float2 q0 = sst[wm][wn ^ 1][g];
    float2 q1 = sst[wm][wn ^ 1][8 + g];
    float M0 = fmaxf(m0, q0.x);
    float S0 = s0 * __expf(m0 - M0) + q0.y * __expf(q0.x - M0);
    float c0 = __expf(m0 - M0) / S0;
    float M1 = fmaxf(m1, q1.x);
    float S1 = s1 * __expf(m1 - M1) + q1.y * __expf(q1.x - M1);
    float c1 = __expf(m1 - M1) / S1;
    // write final fp16 probs (conflict-free: bank = 4g + tg + const)
#pragma unroll
    for (int nt = 0; nt < 4; nt++) {
        int col = wn * 32 + nt * 8 + 2 * tg;
        int row = wm * 16 + g;
        *reinterpret_cast<unsigned*>(Ps + row * 136 + col) =
            pack2(sc[nt][0] * c0, sc[nt][1] * c0);
        *reinterpret_cast<unsigned*>(Ps + (row + 8) * 136 + col) =
            pack2(sc[nt][2] * c1, sc[nt][3] * c1);
    }
    __syncthreads();

    // PV: X_dot = attn @ X; warp tile 16m x 64n, K=64 tokens.
    float acc[8][4];
#pragma unroll
    for (int i = 0; i < 8; i++)
#pragma unroll
        for (int j = 0; j < 4; j++) acc[i][j] = 0.f;
#pragma unroll
    for (int ks = 0; ks < 4; ks++) {
        unsigned a0, a1, a2, a3;
        ldsm_x4(a0, a1, a2, a3, Ps + LDSM_A_OFF(wm * 16, ks * 16, 136));
#pragma unroll
        for (int ntp = 0; ntp < 4; ntp++) {
            unsigned b00, b01, b10, b11;
            ldsm_x4_t(b00, b01, b10, b11,
                      Xn + LDSM_A_OFF(ks * 16, wn * 64 + ntp * 16, 136));
            mma_f16(acc[ntp * 2],     a0, a1, a2, a3, b00, b01);
            mma_f16(acc[ntp * 2 + 1], a0, a1, a2, a3, b10, b11);
        }
    }
    __syncthreads();   // all PV reads of Ps done — safe to overwrite as stage

    // stage PV result (fp16) into Ps region (stride 136)
    __half* Sg = Ps;
#pragma unroll
    for (int nt = 0; nt < 8; nt++) {
        int col = wn * 64 + nt * 8 + 2 * tg;
        int row = wm * 16 + g;
        *reinterpret_cast<unsigned*>(Sg + row * 136 + col) =
            pack2(acc[nt][0], acc[nt][1]);
        *reinterpret_cast<unsigned*>(Sg + (row + 8) * 136 + col) =
            pack2(acc[nt][2], acc[nt][3]);
    }
    __syncthreads();

    // coalesced ypart = stage + X (fp16 adds), uint4 stores
    __half* yp = g_ypart + (size_t)b * TD;
#pragma unroll
    for (int i = 0; i < 4; i++) {
        int q = tid + i * 256;
        int r = q >> 4, o = q & 15;
        uint4 s = *reinterpret_cast<uint4*>(Sg + r * 136 + o * 8);
        uint4 x = *reinterpret_cast<uint4*>(Xn + r * 136 + o * 8);
        uint4 w;
        reinterpret_cast<__half2*>(&w)[0] =
            __hadd2(reinterpret_cast<__half2*>(&s)[0], reinterpret_cast<__half2*>(&x)[0]);
        reinterpret_cast<__half2*>(&w)[1] =
            __hadd2(reinterpret_cast<__half2*>(&s)[1], reinterpret_cast<__half2*>(&x)[1]);
        reinterpret_cast<__half2*>(&w)[2] =
            __hadd2(reinterpret_cast<__half2*>(&s)[2], reinterpret_cast<__half2*>(&x)[2]);
        reinterpret_cast<__half2*>(&w)[3] =
            __hadd2(reinterpret_cast<__half2*>(&s)[3], reinterpret_cast<__half2*>(&x)[3]);
        *reinterpret_cast<uint4*>(yp + r * D + o * 8) = w;
    }
}

// ============================================================
// Kernel 3: out = LN( ypart + b2 + g_ht @ W2^T ) * gamma + beta
// grid (64, 64), 256 thr. M_TILE=64, N=128, K=128. 3 CTAs/SM.
// ypart prefetched via cp.async group 1 (overlaps mainloop).
// smem: As[64][136] + Bs[128][136] + Yp[64][136]; ys fp32 [64][132] aliases As+Bs.
// ============================================================
__global__ void __launch_bounds__(256, 3) gemm2_ln_kernel(
    const float* __restrict__ b2, const float* __restrict__ gamma,
    const float* __restrict__ beta, float* __restrict__ out)
{
    extern __shared__ __half smh[];
    __half* As = smh;                     // 64 x 136
    __half* Bs = smh + 8704;              // 128 x 136
    __half* Yp = smh + 8704 + 17408;      // 64 x 136
    float*  ys = reinterpret_cast<float*>(smh);   // 64 x 132 fp32 (after mma)

    const int m0 = blockIdx.x * 64;
    const int t  = blockIdx.y;
    const int tid = threadIdx.x, wid = tid >> 5, lane = tid & 31;
    const int g = lane >> 2, tg = lane & 3;
    const int l7 = lane & 7, lb8 = (lane >> 3) & 1, lc16 = lane >> 4;
    const int wm = wid & 3, wn = wid >> 2;      // warp tile 16m x 64n

    // group 0: A (relu(h)) + B (W2 token tile)
#pragma unroll
    for (int i = 0; i < 4; i++) {
        int q = tid + i * 256;
        int r = q >> 4, o = q & 15;
        cp16(As + r * 136 + o * 8, g_ht + (size_t)(m0 + r) * D + o * 8);
    }
#pragma unroll
    for (int i = 0; i < 8; i++) {
        int q = tid + i * 256;
        int n = q >> 4, o = q & 15;
        cp16(Bs + n * 136 + o * 8, g_w2h + (size_t)(t * D + n) * D + o * 8);
    }
    asm volatile("cp.async.commit_group;\n");
    // group 1: ypart tile (consumed only in epilogue — overlaps mainloop)
#pragma unroll
    for (int i = 0; i < 4; i++) {
        int q = tid + i * 256;
        int r = q >> 4, o = q & 15;
        cp16(Yp + r * 136 + o * 8, g_ypart + (size_t)(m0 + r) * TD + t * D + o * 8);
    }
    asm volatile("cp.async.commit_group;\n");
    asm volatile("cp.async.wait_group 1;\n");   // A+B ready; Yp may be in flight
    __syncthreads();

    float acc[8][4];
#pragma unroll
    for (int i = 0; i < 8; i++)
#pragma unroll
        for (int j = 0; j < 4; j++) acc[i][j] = 0.f;
#pragma unroll
    for (int ks = 0; ks < 8; ks++) {
        unsigned a0, a1, a2, a3;
        ldsm_x4(a0, a1, a2, a3, As + LDSM_A_OFF(wm * 16, ks * 16, 136));
#pragma unroll
        for (int ntp = 0; ntp < 4; ntp++) {
            unsigned b00, b01, b10, b11;
            ldsm_x4(b00, b01, b10, b11,
                    Bs + LDSM_B_OFF(wn * 64 + ntp * 16, ks * 16, 136));
            mma_f16(acc[ntp * 2],     a0, a1, a2, a3, b00, b01);
            mma_f16(acc[ntp * 2 + 1], a0, a1, a2, a3, b10, b11);
        }
    }
    asm volatile("cp.async.wait_group 0;\n");   // Yp landed
    __syncthreads();                            // mma reads done; As+Bs become ys

    // ys = Yp + b2 (fp32)
#pragma unroll
    for (int i = 0; i < 4; i++) {
        int q = tid + i * 256;
        int r = q >> 4, o = q & 15;
        uint4 u = *reinterpret_cast<uint4*>(Yp + r * 136 + o * 8);
        float4 bb0 = *reinterpret_cast<const float4*>(b2 + t * D + o * 8);
        float4 bb1 = *reinterpret_cast<const float4*>(b2 + t * D + o * 8 + 4);
        float2 f0 = __half22float2(*reinterpret_cast<__half2*>(&u.x));
        float2 f1 = __half22float2(*reinterpret_cast<__half2*>(&u.y));
        float2 f2 = __half22float2(*reinterpret_cast<__half2*>(&u.z));
        float2 f3 = __half22float2(*reinterpret_cast<__half2*>(&u.w));
        *reinterpret_cast<float4*>(ys + r * 132 + o * 8) =
            make_float4(f0.x + bb0.x, f0.y + bb0.y, f1.x + bb0.z, f1.y + bb0.w);
        *reinterpret_cast<float4*>(ys + r * 132 + o * 8 + 4) =
            make_float4(f2.x + bb1.x, f2.y + bb1.y, f3.x + bb1.z, f3.y + bb1.w);
    }
    __syncthreads();
#pragma unroll
    for (int nt = 0; nt < 8; nt++) {
        int row = wm * 16 + g;
        int col = wn * 64 + nt * 8 + 2 * tg;
        ys[row * 132 + col]           += acc[nt][0];
        ys[row * 132 + col + 1]       += acc[nt][1];
        ys[(row + 8) * 132 + col]     += acc[nt][2];
        ys[(row + 8) * 132 + col + 1] += acc[nt][3];
    }
    __syncthreads();

    // LayerNorm; warp owns 8 rows
    float4 gm = *reinterpret_cast<const float4*>(gamma + lane * 4);
    float4 bt = *reinterpret_cast<const float4*>(beta + lane * 4);
    for (int rr = 0; rr < 8; rr++) {
        int r = wid * 8 + rr;
        float4 v = *reinterpret_cast<float4*>(ys + r * 132 + lane * 4);
        float s = v.x + v.y + v.z + v.w;
#pragma unroll
        for (int o = 16; o > 0; o >>= 1) s += __shfl_xor_sync(~0u, s, o);
        float mu = s * (1.f / 128.f);
        float dx = v.x - mu, dy = v.y - mu, dz = v.z - mu, dw = v.w - mu;
        float q2 = dx * dx + dy * dy + dz * dz + dw * dw;
#pragma unroll
        for (int o = 16; o > 0; o >>= 1) q2 += __shfl_xor_sync(~0u, q2, o);
        float rs = rsqrtf(q2 * (1.f / 128.f) + 1e-5f);
        float4 o4;
        o4.x = dx * rs * gm.x + bt.x;
        o4.y = dy * rs * gm.y + bt.y;
        o4.z = dz * rs * gm.z + bt.z;
        o4.w = dw * rs * gm.w + bt.w;
        *reinterpret_cast<float4*>(
            out + (size_t)(m0 + r) * TD + t * D + lane * 4) = o4;
    }
}

// ============================================================
extern "C" void kernel_launch(void* const* d_in, const int* in_sizes, int n_in,
                              void* d_out, int out_size)
{
    const float* X     = (const float*)d_in[0];
    const float* W1    = (const float*)d_in[1];
    const float* b1    = (const float*)d_in[2];
    const float* W2    = (const float*)d_in[3];
    const float* b2    = (const float*)d_in[4];
    const float* gamma = (const float*)d_in[5];
    const float* beta  = (const float*)d_in[6];
    float* out = (float*)d_out;

    const int smem_g1   = 4 * 9216 * 2;                 // 73,728 B
    const int smem_attn = 2 * 8704 * 2;                 // 34,816 B
    const int smem_g2   = (8704 + 17408 + 8704) * 2;    // 69,632 B
    cudaFuncSetAttribute(gemm1_kernel,
        cudaFuncAttributeMaxDynamicSharedMemorySize, smem_g1);
    cudaFuncSetAttribute(attn_kernel,
        cudaFuncAttributeMaxDynamicSharedMemorySize, smem_attn);
    cudaFuncSetAttribute(gemm2_ln_kernel,
        cudaFuncAttributeMaxDynamicSharedMemorySize, smem_g2);

    prep_w_kernel<<<1024, 256>>>(W1, W2);
    gemm1_kernel<<<dim3(32, SPLITK), 256, smem_g1>>>(X);
    reduce_relu_kernel<<<512, 256>>>(b1);
    attn_kernel<<<BATCH, 256, smem_attn>>>(X);
    gemm2_ln_kernel<<<dim3(64, 64), 256, smem_g2>>>(b2, gamma, beta, out);
}

// round 9
// speedup vs baseline: 4.4635x; 1.0371x over previous
#include <cuda_runtime.h>
#include <cuda_fp16.h>
#include <cstdint>

#define BATCH 4096
#define T 64
#define D 128
#define TD 8192
#define SPLITK 8

// Scratch (__device__ globals per allocation-free rule)
__device__ __half g_w1h[(size_t)D * TD];             // W1 fp16, [n][k] (2MB)
__device__ __half g_w2h[(size_t)TD * D];             // W2 fp16, [n][k] (2MB)
__device__ __half g_hp[(size_t)SPLITK * BATCH * D];  // gemm1 partials fp16 (8MB)
__device__ __half g_ht[(size_t)BATCH * D];           // relu(h+b1) fp16 (1MB)
__device__ __half g_ypart[(size_t)BATCH * TD];       // X + X_dot fp16 (64MB)

// ---------------- helpers ----------------
__device__ __forceinline__ unsigned pack2(float lo, float hi) {
    unsigned r;
    asm("cvt.rn.f16x2.f32 %0, %1, %2;" : "=r"(r) : "f"(hi), "f"(lo));
    return r;
}
__device__ __forceinline__ uint4 pack8(float4 v0, float4 v1) {
    uint4 u;
    u.x = pack2(v0.x, v0.y); u.y = pack2(v0.z, v0.w);
    u.z = pack2(v1.x, v1.y); u.w = pack2(v1.z, v1.w);
    return u;
}
__device__ __forceinline__ void mma_f16(float* c,
    unsigned a0, unsigned a1, unsigned a2, unsigned a3, unsigned b0, unsigned b1)
{
    asm volatile(
        "mma.sync.aligned.m16n8k16.row.col.f32.f16.f16.f32 "
        "{%0,%1,%2,%3}, {%4,%5,%6,%7}, {%8,%9}, {%0,%1,%2,%3};\n"
        : "+f"(c[0]), "+f"(c[1]), "+f"(c[2]), "+f"(c[3])
        : "r"(a0), "r"(a1), "r"(a2), "r"(a3), "r"(b0), "r"(b1));
}
__device__ __forceinline__ void cp16(__half* smem_dst, const __half* gsrc) {
    unsigned sa = (unsigned)__cvta_generic_to_shared(smem_dst);
    asm volatile("cp.async.cg.shared.global [%0], [%1], 16;\n" :: "r"(sa), "l"(gsrc));
}
__device__ __forceinline__ void ldsm_x4(unsigned& r0, unsigned& r1,
                                        unsigned& r2, unsigned& r3, const __half* p)
{
    unsigned a = (unsigned)__cvta_generic_to_shared(p);
    asm volatile("ldmatrix.sync.aligned.m8n8.x4.shared.b16 {%0,%1,%2,%3}, [%4];"
        : "=r"(r0), "=r"(r1), "=r"(r2), "=r"(r3) : "r"(a));
}
__device__ __forceinline__ void ldsm_x4_t(unsigned& r0, unsigned& r1,
                                          unsigned& r2, unsigned& r3, const __half* p)
{
    unsigned a = (unsigned)__cvta_generic_to_shared(p);
    asm volatile("ldmatrix.sync.aligned.m8n8.x4.trans.shared.b16 {%0,%1,%2,%3}, [%4];"
        : "=r"(r0), "=r"(r1), "=r"(r2), "=r"(r3) : "r"(a));
}
// A-style ldsm lane offset: 16x16 tile at (R, C), row stride S (halves)
#define LDSM_A_OFF(R, C, S)  (((R) + l7 + lb8 * 8) * (S) + (C) + lc16 * 8)
// B-style (non-trans) lane offset: 16 n-rows at N0, k cols at C
#define LDSM_B_OFF(N0, C, S) (((N0) + lc16 * 8 + l7) * (S) + (C) + lb8 * 8)

// ============================================================
// Prep: W1 (1M) and W2 (1M) fp32 -> fp16, layouts already [n][k]
// ============================================================
__global__ void __launch_bounds__(256) prep_w_kernel(
    const float* __restrict__ W1, const float* __restrict__ W2)
{
    size_t o = (size_t)(blockIdx.x * 256 + threadIdx.x) * 8;
    const size_t NW = (size_t)D * TD;
    const float* src = (o < NW) ? (W1 + o) : (W2 + (o - NW));
    __half* dst = (o < NW) ? (g_w1h + o) : (g_w2h + (o - NW));
    float4 v0 = *reinterpret_cast<const float4*>(src);
    float4 v1 = *reinterpret_cast<const float4*>(src + 4);
    *reinterpret_cast<uint4*>(dst) = pack8(v0, v1);
}

// ============================================================
// Kernel 1: split-K GEMM  h_part = X(4096x8192) @ W1^T (fp16 mma + ldmatrix)
// grid (32, 8), 256 thr. M_TILE=128, N=128, K chunk=1024, K_TILE=64.
// ============================================================
__global__ void __launch_bounds__(256, 2) gemm1_kernel(const float* __restrict__ X)
{
    extern __shared__ __half smh[];
    __half* Asm = smh;                 // 2 stages x 9216 halves (128 x 72)
    __half* Bsm = smh + 2 * 9216;

    const int m0 = blockIdx.x * 128;
    const int k0 = blockIdx.y * 1024;
    const int tid = threadIdx.x;
    const int wid = tid >> 5, lane = tid & 31;
    const int l7 = lane & 7, lb8 = (lane >> 3) & 1, lc16 = lane >> 4;
    const int g = lane >> 2, tg = lane & 3;
    const int wm = wid & 3, wn = wid >> 2;     // warp tile 32m x 64n

    int r4[4], o4[4];
#pragma unroll
    for (int i = 0; i < 4; i++) { int q = tid + i * 256; r4[i] = q >> 3; o4[i] = q & 7; }

    float acc[2][8][4];
#pragma unroll
    for (int m = 0; m < 2; m++)
#pragma unroll
        for (int i = 0; i < 8; i++)
#pragma unroll
            for (int j = 0; j < 4; j++) acc[m][i][j] = 0.f;

    float4 av[4][2];

#define G1_LDA(KK)                                                               \
    {                                                                            \
        _Pragma("unroll")                                                        \
        for (int i = 0; i < 4; i++) {                                            \
            const float* p = X + (size_t)(m0 + r4[i]) * TD + (KK) + o4[i] * 8;   \
            av[i][0] = *reinterpret_cast<const float4*>(p);                      \
            av[i][1] = *reinterpret_cast<const float4*>(p + 4);                  \
        }                                                                        \
    }
#define G1_STA(S)                                                                \
    {                                                                            \
        _Pragma("unroll")                                                        \
        for (int i = 0; i < 4; i++)                                              \
            *reinterpret_cast<uint4*>(Asm + (S) * 9216 + r4[i] * 72 + o4[i] * 8) \
                = pack8(av[i][0], av[i][1]);                                     \
    }
#define G1_CPB(S, KK)                                                            \
    {                                                                            \
        _Pragma("unroll")                                                        \
        for (int i = 0; i < 4; i++)                                              \
            cp16(Bsm + (S) * 9216 + r4[i] * 72 + o4[i] * 8,                      \
                 g_w1h + (size_t)r4[i] * TD + (KK) + o4[i] * 8);                 \
        asm volatile("cp.async.commit_group;\n");                                \
    }

    int kk = k0;
    G1_LDA(kk);
    G1_CPB(0, kk);
    G1_STA(0);
    asm volatile("cp.async.wait_group 0;\n");
    __syncthreads();

    for (int kt = 0; kt < 16; kt++) {
        const int cur = kt & 1, nxt = cur ^ 1;
        if (kt < 15) {
            G1_CPB(nxt, kk + 64);
            G1_LDA(kk + 64);
        }
        const __half* A = Asm + cur * 9216;
        const __half* B = Bsm + cur * 9216;
#pragma unroll
        for (int ks = 0; ks < 4; ks++) {
            unsigned a[2][4];
#pragma unroll
            for (int ms = 0; ms < 2; ms++)
                ldsm_x4(a[ms][0], a[ms][1], a[ms][2], a[ms][3],
                        A + LDSM_A_OFF(wm * 32 + ms * 16, ks * 16, 72));
#pragma unroll
            for (int ntp = 0; ntp < 4; ntp++) {
                unsigned b00, b01, b10, b11;
                ldsm_x4(b00, b01, b10, b11,
                        B + LDSM_B_OFF(wn * 64 + ntp * 16, ks * 16, 72));
#pragma unroll
                for (int ms = 0; ms < 2; ms++) {
                    mma_f16(acc[ms][ntp * 2],     a[ms][0], a[ms][1], a[ms][2], a[ms][3], b00, b01);
                    mma_f16(acc[ms][ntp * 2 + 1], a[ms][0], a[ms][1], a[ms][2], a[ms][3], b10, b11);
                }
            }
        }
        if (kt < 15) {
            G1_STA(nxt);
            asm volatile("cp.async.wait_group 0;\n");
        }
        __syncthreads();
        kk += 64;
    }

    // stage output in smem (stride 136), then coalesced uint4 stores
    __half* Sg = smh;   // 128 x 136 halves
#pragma unroll
    for (int ms = 0; ms < 2; ms++)
#pragma unroll
        for (int nt = 0; nt < 8; nt++) {
            int row = wm * 32 + ms * 16 + g;
            int col = wn * 64 + nt * 8 + 2 * tg;
            *reinterpret_cast<unsigned*>(Sg + row * 136 + col) =
                pack2(acc[ms][nt][0], acc[ms][nt][1]);
            *reinterpret_cast<unsigned*>(Sg + (row + 8) * 136 + col) =
                pack2(acc[ms][nt][2], acc[ms][nt][3]);
        }
    __syncthreads();
    __half* outp = g_hp + (size_t)blockIdx.y * BATCH * D;
#pragma unroll
    for (int i = 0; i < 8; i++) {
        int q = tid + i * 256;
        int r = q >> 4, o = q & 15;
        *reinterpret_cast<uint4*>(outp + (size_t)(m0 + r) * D + o * 8) =
            *reinterpret_cast<uint4*>(Sg + r * 136 + o * 8);
    }
}

// ============================================================
// Kernel 1b: g_ht = fp16( relu( sum_p g_hp[p] + b1 ) )
// ============================================================
__global__ void __launch_bounds__(256) reduce_relu_kernel(const float* __restrict__ b1)
{
    const int idx = blockIdx.x * 256 + threadIdx.x;   // 131072 chunks
    const size_t base = (size_t)idx * 4;
    const int col = (idx & 31) * 4;
    float4 s = *reinterpret_cast<const float4*>(b1 + col);
#pragma unroll
    for (int p = 0; p < SPLITK; p++) {
        uint2 u = *reinterpret_cast<const uint2*>(g_hp + (size_t)p * BATCH * D + base);
        float2 f0 = __half22float2(*reinterpret_cast<__half2*>(&u.x));
        float2 f1 = __half22float2(*reinterpret_cast<__half2*>(&u.y));
        s.x += f0.x; s.y += f0.y; s.z += f1.x; s.w += f1.y;
    }
    s.x = fmaxf(s.x, 0.f); s.y = fmaxf(s.y, 0.f);
    s.z = fmaxf(s.z, 0.f); s.w = fmaxf(s.w, 0.f);
    uint2 o;
    o.x = pack2(s.x, s.y);
    o.y = pack2(s.z, s.w);
    *reinterpret_cast<uint2*>(g_ht + base) = o;
}

// ============================================================
// Kernel 2: per-batch attention (fp16 mma + ldmatrix + register softmax)
// ============================================================
__global__ void __launch_bounds__(256, 4) attn_kernel(const float* __restrict__ X)
{
    extern __shared__ __half smh[];
    __half* Xn = smh;                  // 64 x 136
    __half* Ps = smh + 8704;           // 64 x 136 (fp16 probs; stage alias later)
    __shared__ float2 sst[4][2][16];   // (wm, wn, row-in-warp) partial (max, sum)

    const int b = blockIdx.x;
    const float* Xb = X + (size_t)b * TD;
    const int tid = threadIdx.x, wid = tid >> 5, lane = tid & 31;
    const int g = lane >> 2, tg = lane & 3;
    const int l7 = lane & 7, lb8 = (lane >> 3) & 1, lc16 = lane >> 4;
    const int wm = wid & 3, wn = wid >> 2;

    // fill Xn (convert fp32 -> fp16)
#pragma unroll
    for (int i = 0; i < 4; i++) {
        int q = tid + i * 256;
        int r = q >> 4, o = q & 15;
        const float* p = Xb + r * D + o * 8;
        float4 v0 = *reinterpret_cast<const float4*>(p);
        float4 v1 = *reinterpret_cast<const float4*>(p + 4);
        *reinterpret_cast<uint4*>(Xn + r * 136 + o * 8) = pack8(v0, v1);
    }
    __syncthreads();

    // QK: scores = X X^T * scale; warp tile 16m x 32n — kept in registers
    float sc[4][4];
#pragma unroll
    for (int i = 0; i < 4; i++)
#pragma unroll
        for (int j = 0; j < 4; j++) sc[i][j] = 0.f;
#pragma unroll
    for (int ks = 0; ks < 8; ks++) {
        unsigned a0, a1, a2, a3;
        ldsm_x4(a0, a1, a2, a3, Xn + LDSM_A_OFF(wm * 16, ks * 16, 136));
#pragma unroll
        for (int ntp = 0; ntp < 2; ntp++) {
            unsigned b00, b01, b10, b11;
            ldsm_x4(b00, b01, b10, b11,
                    Xn + LDSM_B_OFF(wn * 32 + ntp * 16, ks * 16, 136));
            mma_f16(sc[ntp * 2],     a0, a1, a2, a3, b00, b01);
            mma_f16(sc[ntp * 2 + 1], a0, a1, a2, a3, b10, b11);
        }
    }

    // ---- register softmax ----
    const float scale = 0.0883883476483184f;   // 128^-0.5
    float m0 = -1e30f, m1 = -1e30f;
#pragma unroll
    for (int nt = 0; nt < 4; nt++) {
        sc[nt][0] *= scale; sc[nt][1] *= scale;
        sc[nt][2] *= scale; sc[nt][3] *= scale;
        m0 = fmaxf(m0, fmaxf(sc[nt][0], sc[nt][1]));
        m1 = fmaxf(m1, fmaxf(sc[nt][2], sc[nt][3]));
    }
    m0 = fmaxf(m0, __shfl_xor_sync(~0u, m0, 1));
    m0 = fmaxf(m0, __shfl_xor_sync(~0u, m0, 2));
    m1 = fmaxf(m1, __shfl_xor_sync(~0u, m1, 1));
    m1 = fmaxf(m1, __shfl_xor_sync(~0u, m1, 2));
    float s0 = 0.f, s1 = 0.f;
#pragma unroll
    for (int nt = 0; nt < 4; nt++) {
        sc[nt][0] = __expf(sc[nt][0] - m0); s0 += sc[nt][0];
        sc[nt][1] = __expf(sc[nt][1] - m0); s0 += sc[nt][1];
        sc[nt][2] = __expf(sc[nt][2] - m1); s1 += sc[nt][2];
        sc[nt][3] = __expf(sc[nt][3] - m1); s1 += sc[nt][3];
    }
    s0 += __shfl_xor_sync(~0u, s0, 1); s0 += __shfl_xor_sync(~0u, s0, 2);
    s1 += __shfl_xor_sync(~0u, s1, 1); s1 += __shfl_xor_sync(~0u, s1, 2);
    if (tg == 0) {
        sst[wm][wn][g]     = make_float2(m0, s0);
        sst[wm][wn][8 + g] = make_float2(m1, s1);
    }
    __syncthreads();
    float2 q0 = sst[wm][wn ^ 1][g];
    float2 q1 = sst[wm][wn ^ 1][8 + g];
    float M0 = fmaxf(m0, q0.x);
    float S0 = s0 * __expf(m0 - M0) + q0.y * __expf(q0.x - M0);
    float c0 = __expf(m0 - M0) / S0;
    float M1 = fmaxf(m1, q1.x);
    float S1 = s1 * __expf(m1 - M1) + q1.y * __expf(q1.x - M1);
    float c1 = __expf(m1 - M1) / S1;
#pragma unroll
    for (int nt = 0; nt < 4; nt++) {
        int col = wn * 32 + nt * 8 + 2 * tg;
        int row = wm * 16 + g;
        *reinterpret_cast<unsigned*>(Ps + row * 136 + col) =
            pack2(sc[nt][0] * c0, sc[nt][1] * c0);
        *reinterpret_cast<unsigned*>(Ps + (row + 8) * 136 + col) =
            pack2(sc[nt][2] * c1, sc[nt][3] * c1);
    }
    __syncthreads();

    // PV: X_dot = attn @ X; warp tile 16m x 64n, K=64 tokens.
    float acc[8][4];
#pragma unroll
    for (int i = 0; i < 8; i++)
#pragma unroll
        for (int j = 0; j < 4; j++) acc[i][j] = 0.f;
#pragma unroll
    for (int ks = 0; ks < 4; ks++) {
        unsigned a0, a1, a2, a3;
        ldsm_x4(a0, a1, a2, a3, Ps + LDSM_A_OFF(wm * 16, ks * 16, 136));
#pragma unroll
        for (int ntp = 0; ntp < 4; ntp++) {
            unsigned b00, b01, b10, b11;
            ldsm_x4_t(b00, b01, b10, b11,
                      Xn + LDSM_A_OFF(ks * 16, wn * 64 + ntp * 16, 136));
            mma_f16(acc[ntp * 2],     a0, a1, a2, a3, b00, b01);
            mma_f16(acc[ntp * 2 + 1], a0, a1, a2, a3, b10, b11);
        }
    }
    __syncthreads();   // all PV reads of Ps done — safe to overwrite as stage

    // stage PV result (fp16) into Ps region (stride 136)
    __half* Sg = Ps;
#pragma unroll
    for (int nt = 0; nt < 8; nt++) {
        int col = wn * 64 + nt * 8 + 2 * tg;
        int row = wm * 16 + g;
        *reinterpret_cast<unsigned*>(Sg + row * 136 + col) =
            pack2(acc[nt][0], acc[nt][1]);
        *reinterpret_cast<unsigned*>(Sg + (row + 8) * 136 + col) =
            pack2(acc[nt][2], acc[nt][3]);
    }
    __syncthreads();

    // coalesced ypart = stage + X (fp16 adds), uint4 stores
    __half* yp = g_ypart + (size_t)b * TD;
#pragma unroll
    for (int i = 0; i < 4; i++) {
        int q = tid + i * 256;
        int r = q >> 4, o = q & 15;
        uint4 s = *reinterpret_cast<uint4*>(Sg + r * 136 + o * 8);
        uint4 x = *reinterpret_cast<uint4*>(Xn + r * 136 + o * 8);
        uint4 w;
        reinterpret_cast<__half2*>(&w)[0] =
            __hadd2(reinterpret_cast<__half2*>(&s)[0], reinterpret_cast<__half2*>(&x)[0]);
        reinterpret_cast<__half2*>(&w)[1] =
            __hadd2(reinterpret_cast<__half2*>(&s)[1], reinterpret_cast<__half2*>(&x)[1]);
        reinterpret_cast<__half2*>(&w)[2] =
            __hadd2(reinterpret_cast<__half2*>(&s)[2], reinterpret_cast<__half2*>(&x)[2]);
        reinterpret_cast<__half2*>(&w)[3] =
            __hadd2(reinterpret_cast<__half2*>(&s)[3], reinterpret_cast<__half2*>(&x)[3]);
        *reinterpret_cast<uint4*>(yp + r * D + o * 8) = w;
    }
}

// ============================================================
// Kernel 3: out = LN( ypart + b2 + g_ht @ W2^T ) * gamma + beta
// grid (32, 64), 256 thr. M_TILE=128, N=128, K=128 (reverted to best config).
// smem: As[128][136] + Bs[128][136] + Yp[128][136]; ys fp32 [128][132] aliases As+Bs.
// ============================================================
__global__ void __launch_bounds__(256, 2) gemm2_ln_kernel(
    const float* __restrict__ b2, const float* __restrict__ gamma,
    const float* __restrict__ beta, float* __restrict__ out)
{
    extern __shared__ __half smh[];
    __half* As = smh;                     // 128 x 136
    __half* Bs = smh + 17408;             // 128 x 136
    __half* Yp = smh + 34816;             // 128 x 136
    float*  ys = reinterpret_cast<float*>(smh);   // 128 x 132 fp32 (after mma)

    const int m0 = blockIdx.x * 128;
    const int t  = blockIdx.y;
    const int tid = threadIdx.x, wid = tid >> 5, lane = tid & 31;
    const int g = lane >> 2, tg = lane & 3;
    const int l7 = lane & 7, lb8 = (lane >> 3) & 1, lc16 = lane >> 4;
    const int wm = wid & 3, wn = wid >> 2;      // warp tile 32m x 64n

    // group 0: A (relu(h)) + B (W2 token tile)
#pragma unroll
    for (int i = 0; i < 8; i++) {
        int q = tid + i * 256;
        int r = q >> 4, o = q & 15;
        cp16(As + r * 136 + o * 8, g_ht + (size_t)(m0 + r) * D + o * 8);
        cp16(Bs + r * 136 + o * 8, g_w2h + (size_t)(t * D + r) * D + o * 8);
    }
    asm volatile("cp.async.commit_group;\n");
    // group 1: ypart tile (consumed only in epilogue — overlaps mainloop)
#pragma unroll
    for (int i = 0; i < 8; i++) {
        int q = tid + i * 256;
        int r = q >> 4, o = q & 15;
        cp16(Yp + r * 136 + o * 8, g_ypart + (size_t)(m0 + r) * TD + t * D + o * 8);
    }
    asm volatile("cp.async.commit_group;\n");
    asm volatile("cp.async.wait_group 1;\n");   // A+B ready; Yp may be in flight
    __syncthreads();

    float acc[2][8][4];
#pragma unroll
    for (int m = 0; m < 2; m++)
#pragma unroll
        for (int i = 0; i < 8; i++)
#pragma unroll
            for (int j = 0; j < 4; j++) acc[m][i][j] = 0.f;

#pragma unroll
    for (int ks = 0; ks < 8; ks++) {
        unsigned a[2][4];
#pragma unroll
        for (int ms = 0; ms < 2; ms++)
            ldsm_x4(a[ms][0], a[ms][1], a[ms][2], a[ms][3],
                    As + LDSM_A_OFF(wm * 32 + ms * 16, ks * 16, 136));
#pragma unroll
        for (int ntp = 0; ntp < 4; ntp++) {
            unsigned b00, b01, b10, b11;
            ldsm_x4(b00, b01, b10, b11,
                    Bs + LDSM_B_OFF(wn * 64 + ntp * 16, ks * 16, 136));
#pragma unroll
            for (int ms = 0; ms < 2; ms++) {
                mma_f16(acc[ms][ntp * 2],     a[ms][0], a[ms][1], a[ms][2], a[ms][3], b00, b01);
                mma_f16(acc[ms][ntp * 2 + 1], a[ms][0], a[ms][1], a[ms][2], a[ms][3], b10, b11);
            }
        }
    }
    asm volatile("cp.async.wait_group 0;\n");   // Yp landed
    __syncthreads();                            // mma reads done; As+Bs become ys

    // ys = Yp + b2 (fp32)
#pragma unroll
    for (int i = 0; i < 8; i++) {
        int q = tid + i * 256;
        int r = q >> 4, o = q & 15;
        uint4 u = *reinterpret_cast<uint4*>(Yp + r * 136 + o * 8);
        float4 bb0 = *reinterpret_cast<const float4*>(b2 + t * D + o * 8);
        float4 bb1 = *reinterpret_cast<const float4*>(b2 + t * D + o * 8 + 4);
        float2 f0 = __half22float2(*reinterpret_cast<__half2*>(&u.x));
        float2 f1 = __half22float2(*reinterpret_cast<__half2*>(&u.y));
        float2 f2 = __half22float2(*reinterpret_cast<__half2*>(&u.z));
        float2 f3 = __half22float2(*reinterpret_cast<__half2*>(&u.w));
        *reinterpret_cast<float4*>(ys + r * 132 + o * 8) =
            make_float4(f0.x + bb0.x, f0.y + bb0.y, f1.x + bb0.z, f1.y + bb0.w);
        *reinterpret_cast<float4*>(ys + r * 132 + o * 8 + 4) =
            make_float4(f2.x + bb1.x, f2.y + bb1.y, f3.x + bb1.z, f3.y + bb1.w);
    }
    __syncthreads();
#pragma unroll
    for (int ms = 0; ms < 2; ms++)
#pragma unroll
        for (int nt = 0; nt < 8; nt++) {
            int row = wm * 32 + ms * 16 + g;
            int col = wn * 64 + nt * 8 + 2 * tg;
            ys[row * 132 + col]           += acc[ms][nt][0];
            ys[row * 132 + col + 1]       += acc[ms][nt][1];
            ys[(row + 8) * 132 + col]     += acc[ms][nt][2];
            ys[(row + 8) * 132 + col + 1] += acc[ms][nt][3];
        }
    __syncthreads();

    // LayerNorm; warp owns 16 rows
    float4 gm = *reinterpret_cast<const float4*>(gamma + lane * 4);
    float4 bt = *reinterpret_cast<const float4*>(beta + lane * 4);
    for (int rr = 0; rr < 16; rr++) {
        int r = wid * 16 + rr;
        float4 v = *reinterpret_cast<float4*>(ys + r * 132 + lane * 4);
        float s = v.x + v.y + v.z + v.w;
#pragma unroll
        for (int o = 16; o > 0; o >>= 1) s += __shfl_xor_sync(~0u, s, o);
        float mu = s * (1.f / 128.f);
        float dx = v.x - mu, dy = v.y - mu, dz = v.z - mu, dw = v.w - mu;
        float q2 = dx * dx + dy * dy + dz * dz + dw * dw;
#pragma unroll
        for (int o = 16; o > 0; o >>= 1) q2 += __shfl_xor_sync(~0u, q2, o);
        float rs = rsqrtf(q2 * (1.f / 128.f) + 1e-5f);
        float4 o4;
        o4.x = dx * rs * gm.x + bt.x;
        o4.y = dy * rs * gm.y + bt.y;
        o4.z = dz * rs * gm.z + bt.z;
        o4.w = dw * rs * gm.w + bt.w;
        *reinterpret_cast<float4*>(
            out + (size_t)(m0 + r) * TD + t * D + lane * 4) = o4;
    }
}

// ============================================================
// Launcher: attn runs concurrently with prep->gemm1->reduce on a second
// stream (event fork/join — graph-capturable, no allocs, no syncs).
// ============================================================
extern "C" void kernel_launch(void* const* d_in, const int* in_sizes, int n_in,
                              void* d_out, int out_size)
{
    const float* X     = (const float*)d_in[0];
    const float* W1    = (const float*)d_in[1];
    const float* b1    = (const float*)d_in[2];
    const float* W2    = (const float*)d_in[3];
    const float* b2    = (const float*)d_in[4];
    const float* gamma = (const float*)d_in[5];
    const float* beta  = (const float*)d_in[6];
    float* out = (float*)d_out;

    const int smem_g1   = 4 * 9216 * 2;                 // 73,728 B
    const int smem_attn = 2 * 8704 * 2;                 // 34,816 B
    const int smem_g2   = 3 * 17408 * 2;                // 104,448 B
    cudaFuncSetAttribute(gemm1_kernel,
        cudaFuncAttributeMaxDynamicSharedMemorySize, smem_g1);
    cudaFuncSetAttribute(attn_kernel,
        cudaFuncAttributeMaxDynamicSharedMemorySize, smem_attn);
    cudaFuncSetAttribute(gemm2_ln_kernel,
        cudaFuncAttributeMaxDynamicSharedMemorySize, smem_g2);

    cudaStream_t s2;
    cudaStreamCreateWithFlags(&s2, cudaStreamNonBlocking);
    cudaEvent_t eFork, eJoin;
    cudaEventCreateWithFlags(&eFork, cudaEventDisableTiming);
    cudaEventCreateWithFlags(&eJoin, cudaEventDisableTiming);

    // fork: attn (depends only on X) on s2
    cudaEventRecord(eFork, 0);
    cudaStreamWaitEvent(s2, eFork, 0);
    attn_kernel<<<BATCH, 256, smem_attn, s2>>>(X);
    cudaEventRecord(eJoin, s2);

    // main chain: prep -> gemm1 -> reduce
    prep_w_kernel<<<1024, 256>>>(W1, W2);
    gemm1_kernel<<<dim3(32, SPLITK), 256, smem_g1>>>(X);
    reduce_relu_kernel<<<512, 256>>>(b1);

    // join, then gemm2 (needs ht + ypart)
    cudaStreamWaitEvent(0, eJoin, 0);
    gemm2_ln_kernel<<<dim3(32, 64), 256, smem_g2>>>(b2, gamma, beta, out);
}